// round 1
// baseline (speedup 1.0000x reference)
#include <cuda_runtime.h>
#include <math.h>

#define Nn 2
#define Ss 2048
#define Dd 1024
#define Hh 16
#define DH 64
#define BQ 64
#define BK 64
#define PAD 68   // floats per smem row: %4==0 (float4) and conflict-free under our mapping

// Scratch QKV in [N,H,S,DH] layout (attention-friendly). ~16MB each, device globals
// per the no-allocation rule.
__device__ float g_q[(size_t)Nn*Hh*Ss*DH];
__device__ float g_k[(size_t)Nn*Hh*Ss*DH];
__device__ float g_v[(size_t)Nn*Hh*Ss*DH];

// ---------------------------------------------------------------------------
// Kernel 1: per-head QKV projection.
// Block = 64 sequence rows x 1 head. 256 threads: r = tid>>2 (row), t4 = tid&3.
// Thread computes outputs e = t4 + 4*i (i=0..15) for all of q,k,v.
// ---------------------------------------------------------------------------
__global__ void qkv_proj_kernel(const float* __restrict__ x,
                                const float* __restrict__ Wq, const float* __restrict__ bq,
                                const float* __restrict__ Wk, const float* __restrict__ bk,
                                const float* __restrict__ Wv, const float* __restrict__ bv)
{
    extern __shared__ float sm[];
    float* xs  = sm;                 // 64*PAD
    float* wqs = xs  + BQ*PAD;
    float* wks = wqs + BQ*PAD;
    float* wvs = wks + BQ*PAD;

    const int s0  = blockIdx.x * BQ;
    const int h   = blockIdx.y;
    const int n   = blockIdx.z;
    const int tid = threadIdx.x;

    const float* xg  = x  + ((size_t)(n*Ss + s0))*Dd + h*DH;
    const float* wqg = Wq + (size_t)h*DH*DH;
    const float* wkg = Wk + (size_t)h*DH*DH;
    const float* wvg = Wv + (size_t)h*DH*DH;

    #pragma unroll
    for (int it = 0; it < 4; it++) {
        int idx = tid + 256*it;          // float4 index, 0..1023
        int row = idx >> 4;              // 16 float4 per 64-float row
        int dd  = idx & 15;
        *(float4*)(xs  + row*PAD + 4*dd) = *(const float4*)(xg  + (size_t)row*Dd + 4*dd);
        *(float4*)(wqs + row*PAD + 4*dd) = *(const float4*)(wqg + row*DH + 4*dd);
        *(float4*)(wks + row*PAD + 4*dd) = *(const float4*)(wkg + row*DH + 4*dd);
        *(float4*)(wvs + row*PAD + 4*dd) = *(const float4*)(wvg + row*DH + 4*dd);
    }
    __syncthreads();

    const int r  = tid >> 2;
    const int t4 = tid & 3;

    float aq[16], ak[16], av[16];
    #pragma unroll
    for (int i = 0; i < 16; i++) {
        int e = t4 + 4*i;
        aq[i] = bq[h*DH + e];
        ak[i] = bk[h*DH + e];
        av[i] = bv[h*DH + e];
    }

    for (int d4 = 0; d4 < 16; d4++) {
        float4 x4 = *(const float4*)(xs + r*PAD + 4*d4);
        #pragma unroll
        for (int i = 0; i < 16; i++) {
            int e = t4 + 4*i;
            float4 w;
            w = *(const float4*)(wqs + e*PAD + 4*d4);
            aq[i] += x4.x*w.x + x4.y*w.y + x4.z*w.z + x4.w*w.w;
            w = *(const float4*)(wks + e*PAD + 4*d4);
            ak[i] += x4.x*w.x + x4.y*w.y + x4.z*w.z + x4.w*w.w;
            w = *(const float4*)(wvs + e*PAD + 4*d4);
            av[i] += x4.x*w.x + x4.y*w.y + x4.z*w.z + x4.w*w.w;
        }
    }

    const size_t base = ((size_t)((n*Hh + h))*Ss + s0 + r)*DH;
    #pragma unroll
    for (int i = 0; i < 16; i++) {
        int e = t4 + 4*i;
        g_q[base + e] = aq[i];
        g_k[base + e] = ak[i];
        g_v[base + e] = av[i];
    }
}

// ---------------------------------------------------------------------------
// Kernel 2: fused flash attention (fp32, online softmax).
// Block = (n, h, 64-query tile). 256 threads: r = tid>>2 query row, t4 = tid&3.
// Score phase: thread owns keys j = t4 + 4*i.
// PV phase:    thread owns output cols e = t4*4 + 16*ii + jj.
// Both mappings are smem-bank conflict-free with PAD=68.
// ---------------------------------------------------------------------------
__global__ void attn_kernel(float* __restrict__ out)
{
    extern __shared__ float sm[];
    float* Qs = sm;                  // BQ*PAD
    float* Ks = Qs + BQ*PAD;
    float* Vs = Ks + BK*PAD;
    float* Ps = Vs + BK*PAD;

    const int q0  = blockIdx.x * BQ;
    const int h   = blockIdx.y;
    const int n   = blockIdx.z;
    const int tid = threadIdx.x;
    const int r   = tid >> 2;
    const int t4  = tid & 3;

    const size_t head_off = (size_t)(n*Hh + h) * Ss * DH;
    const float* qg = g_q + head_off;
    const float* kg = g_k + head_off;
    const float* vg = g_v + head_off;

    // load Q tile, folding the 1/sqrt(DH)=0.125 scale into Q
    #pragma unroll
    for (int it = 0; it < 4; it++) {
        int idx = tid + 256*it;
        int row = idx >> 4, dd = idx & 15;
        float4 v = *(const float4*)(qg + (size_t)(q0+row)*DH + 4*dd);
        v.x *= 0.125f; v.y *= 0.125f; v.z *= 0.125f; v.w *= 0.125f;
        *(float4*)(Qs + row*PAD + 4*dd) = v;
    }

    float acc[16];
    #pragma unroll
    for (int i = 0; i < 16; i++) acc[i] = 0.f;
    float m = -1e30f, l = 0.f;

    __syncthreads();

    for (int k0 = 0; k0 < Ss; k0 += BK) {
        // load K,V tiles
        #pragma unroll
        for (int it = 0; it < 4; it++) {
            int idx = tid + 256*it;
            int row = idx >> 4, dd = idx & 15;
            *(float4*)(Ks + row*PAD + 4*dd) = *(const float4*)(kg + (size_t)(k0+row)*DH + 4*dd);
            *(float4*)(Vs + row*PAD + 4*dd) = *(const float4*)(vg + (size_t)(k0+row)*DH + 4*dd);
        }
        __syncthreads();

        // scores: s[i] = q_r . k_{t4+4i}  (already scaled)
        float s[16];
        #pragma unroll
        for (int i = 0; i < 16; i++) s[i] = 0.f;
        #pragma unroll 4
        for (int d4 = 0; d4 < 16; d4++) {
            float4 q4 = *(const float4*)(Qs + r*PAD + 4*d4);
            #pragma unroll
            for (int i = 0; i < 16; i++) {
                int j = t4 + 4*i;
                float4 k4 = *(const float4*)(Ks + j*PAD + 4*d4);
                s[i] += q4.x*k4.x + q4.y*k4.y + q4.z*k4.z + q4.w*k4.w;
            }
        }

        // online softmax: reduce across the 4 lanes sharing row r (lanes 4r..4r+3)
        float tmax = s[0];
        #pragma unroll
        for (int i = 1; i < 16; i++) tmax = fmaxf(tmax, s[i]);
        tmax = fmaxf(tmax, __shfl_xor_sync(0xffffffffu, tmax, 1));
        tmax = fmaxf(tmax, __shfl_xor_sync(0xffffffffu, tmax, 2));
        float mnew  = fmaxf(m, tmax);
        float alpha = __expf(m - mnew);
        float tsum = 0.f;
        #pragma unroll
        for (int i = 0; i < 16; i++) {
            float p = __expf(s[i] - mnew);
            Ps[r*PAD + t4 + 4*i] = p;
            tsum += p;
        }
        tsum += __shfl_xor_sync(0xffffffffu, tsum, 1);
        tsum += __shfl_xor_sync(0xffffffffu, tsum, 2);
        m = mnew;
        l = l*alpha + tsum;
        #pragma unroll
        for (int i = 0; i < 16; i++) acc[i] *= alpha;
        __syncthreads();

        // acc += P[r,:] @ V ; thread owns cols t4*4 + 16*ii + jj
        #pragma unroll 4
        for (int k4 = 0; k4 < 16; k4++) {
            float4 p4 = *(const float4*)(Ps + r*PAD + 4*k4);
            #pragma unroll
            for (int kk = 0; kk < 4; kk++) {
                int   k  = 4*k4 + kk;
                float pv = (kk == 0) ? p4.x : (kk == 1) ? p4.y : (kk == 2) ? p4.z : p4.w;
                #pragma unroll
                for (int ii = 0; ii < 4; ii++) {
                    float4 v4 = *(const float4*)(Vs + k*PAD + t4*4 + 16*ii);
                    acc[4*ii+0] += pv*v4.x;
                    acc[4*ii+1] += pv*v4.y;
                    acc[4*ii+2] += pv*v4.z;
                    acc[4*ii+3] += pv*v4.w;
                }
            }
        }
        __syncthreads();
    }

    const float inv = 1.f / l;
    float* og = out + ((size_t)n*Ss + q0 + r)*Dd + h*DH;
    #pragma unroll
    for (int ii = 0; ii < 4; ii++) {
        float4 v;
        v.x = acc[4*ii+0]*inv;
        v.y = acc[4*ii+1]*inv;
        v.z = acc[4*ii+2]*inv;
        v.w = acc[4*ii+3]*inv;
        *(float4*)(og + t4*4 + 16*ii) = v;
    }
}

// ---------------------------------------------------------------------------
extern "C" void kernel_launch(void* const* d_in, const int* in_sizes, int n_in,
                              void* d_out, int out_size)
{
    const float* x  = (const float*)d_in[0];
    const float* Wq = (const float*)d_in[1];
    const float* bq = (const float*)d_in[2];
    const float* Wk = (const float*)d_in[3];
    const float* bk = (const float*)d_in[4];
    const float* Wv = (const float*)d_in[5];
    const float* bv = (const float*)d_in[6];
    float* out = (float*)d_out;

    const int smem = 4 * BQ * PAD * (int)sizeof(float);   // 69632 bytes
    cudaFuncSetAttribute(qkv_proj_kernel, cudaFuncAttributeMaxDynamicSharedMemorySize, smem);
    cudaFuncSetAttribute(attn_kernel,     cudaFuncAttributeMaxDynamicSharedMemorySize, smem);

    dim3 grid(Ss/BQ, Hh, Nn);   // (32, 16, 2)
    qkv_proj_kernel<<<grid, 256, smem>>>(x, Wq, bq, Wk, bk, Wv, bv);
    attn_kernel<<<grid, 256, smem>>>(out);
}

// round 2
// speedup vs baseline: 1.8801x; 1.8801x over previous
#include <cuda_runtime.h>
#include <math.h>

#define Nn 2
#define Ss 2048
#define Dd 1024
#define Hh 16
#define DH 64
#define BQ 64
#define BK 64
#define PAD 68   // floats per smem row: %4==0 (float4-aligned), near-conflict-free

// Scratch QKV in [N,H,S,DH] layout. Device globals per the no-allocation rule.
__device__ float g_q[(size_t)Nn*Hh*Ss*DH];
__device__ float g_k[(size_t)Nn*Hh*Ss*DH];
__device__ float g_v[(size_t)Nn*Hh*Ss*DH];

// ---------------------------------------------------------------------------
// Kernel 1: per-head QKV projection (unchanged from R1; ~5% of runtime).
// ---------------------------------------------------------------------------
__global__ void qkv_proj_kernel(const float* __restrict__ x,
                                const float* __restrict__ Wq, const float* __restrict__ bq,
                                const float* __restrict__ Wk, const float* __restrict__ bk,
                                const float* __restrict__ Wv, const float* __restrict__ bv)
{
    extern __shared__ float sm[];
    float* xs  = sm;                 // 64*PAD
    float* wqs = xs  + BQ*PAD;
    float* wks = wqs + BQ*PAD;
    float* wvs = wks + BQ*PAD;

    const int s0  = blockIdx.x * BQ;
    const int h   = blockIdx.y;
    const int n   = blockIdx.z;
    const int tid = threadIdx.x;

    const float* xg  = x  + ((size_t)(n*Ss + s0))*Dd + h*DH;
    const float* wqg = Wq + (size_t)h*DH*DH;
    const float* wkg = Wk + (size_t)h*DH*DH;
    const float* wvg = Wv + (size_t)h*DH*DH;

    #pragma unroll
    for (int it = 0; it < 4; it++) {
        int idx = tid + 256*it;          // float4 index, 0..1023
        int row = idx >> 4;
        int dd  = idx & 15;
        *(float4*)(xs  + row*PAD + 4*dd) = *(const float4*)(xg  + (size_t)row*Dd + 4*dd);
        *(float4*)(wqs + row*PAD + 4*dd) = *(const float4*)(wqg + row*DH + 4*dd);
        *(float4*)(wks + row*PAD + 4*dd) = *(const float4*)(wkg + row*DH + 4*dd);
        *(float4*)(wvs + row*PAD + 4*dd) = *(const float4*)(wvg + row*DH + 4*dd);
    }
    __syncthreads();

    const int r  = tid >> 2;
    const int t4 = tid & 3;

    float aq[16], ak[16], av[16];
    #pragma unroll
    for (int i = 0; i < 16; i++) {
        int e = t4 + 4*i;
        aq[i] = bq[h*DH + e];
        ak[i] = bk[h*DH + e];
        av[i] = bv[h*DH + e];
    }

    for (int d4 = 0; d4 < 16; d4++) {
        float4 x4 = *(const float4*)(xs + r*PAD + 4*d4);
        #pragma unroll
        for (int i = 0; i < 16; i++) {
            int e = t4 + 4*i;
            float4 w;
            w = *(const float4*)(wqs + e*PAD + 4*d4);
            aq[i] += x4.x*w.x + x4.y*w.y + x4.z*w.z + x4.w*w.w;
            w = *(const float4*)(wks + e*PAD + 4*d4);
            ak[i] += x4.x*w.x + x4.y*w.y + x4.z*w.z + x4.w*w.w;
            w = *(const float4*)(wvs + e*PAD + 4*d4);
            av[i] += x4.x*w.x + x4.y*w.y + x4.z*w.z + x4.w*w.w;
        }
    }

    const size_t base = ((size_t)((n*Hh + h))*Ss + s0 + r)*DH;
    #pragma unroll
    for (int i = 0; i < 16; i++) {
        int e = t4 + 4*i;
        g_q[base + e] = aq[i];
        g_k[base + e] = ak[i];
        g_v[base + e] = av[i];
    }
}

// ---------------------------------------------------------------------------
// Kernel 2: fused flash attention, register-blocked.
// 128 threads/block. Thread tile: 4 query rows x 8 keys (scores) and
// 4 query rows x 8 output cols (PV). rg = tid>>3 (row group), kg = tid&7.
// K tile is XOR-swizzled in smem (float4 idx ^= row>>3) so the 8-distinct-row
// K load in the score loop is bank-conflict-free.
// ---------------------------------------------------------------------------
__global__ void __launch_bounds__(128, 3) attn_kernel(float* __restrict__ out)
{
    extern __shared__ float sm[];
    float* Qs = sm;                  // BQ*PAD
    float* Ks = Qs + BQ*PAD;         // swizzled
    float* Vs = Ks + BK*PAD;
    float* Ps = Vs + BK*PAD;

    const int q0  = blockIdx.x * BQ;
    const int h   = blockIdx.y;
    const int n   = blockIdx.z;
    const int tid = threadIdx.x;
    const int rg  = tid >> 3;        // 0..15 -> rows 4rg..4rg+3
    const int kg  = tid & 7;         // 0..7  -> keys/cols 8kg..8kg+7

    const size_t head_off = (size_t)(n*Hh + h) * Ss * DH;
    const float* qg = g_q + head_off;
    const float* kgp = g_k + head_off;
    const float* vg = g_v + head_off;

    // load Q tile (scale 1/sqrt(DH)=0.125 folded in): 8 float4 per thread
    #pragma unroll
    for (int it = 0; it < 8; it++) {
        int idx = tid + 128*it;      // 0..1023
        int row = idx >> 4, dd = idx & 15;
        float4 v = *(const float4*)(qg + (size_t)(q0+row)*DH + 4*dd);
        v.x *= 0.125f; v.y *= 0.125f; v.z *= 0.125f; v.w *= 0.125f;
        *(float4*)(Qs + row*PAD + 4*dd) = v;
    }

    float acc[32];
    #pragma unroll
    for (int i = 0; i < 32; i++) acc[i] = 0.f;
    float m[4], l[4];
    #pragma unroll
    for (int rr = 0; rr < 4; rr++) { m[rr] = -1e30f; l[rr] = 0.f; }

    __syncthreads();

    for (int k0 = 0; k0 < Ss; k0 += BK) {
        // load K (swizzled) and V tiles: 8 float4 each per thread
        #pragma unroll
        for (int it = 0; it < 8; it++) {
            int idx = tid + 128*it;
            int row = idx >> 4, dd = idx & 15;
            int sw  = dd ^ ((row >> 3) & 7);
            *(float4*)(Ks + row*PAD + 4*sw) = *(const float4*)(kgp + (size_t)(k0+row)*DH + 4*dd);
            *(float4*)(Vs + row*PAD + 4*dd) = *(const float4*)(vg  + (size_t)(k0+row)*DH + 4*dd);
        }
        __syncthreads();

        // scores: s[rr][kk] = q_{4rg+rr} . k_{8kg+kk}
        float s[4][8];
        #pragma unroll
        for (int rr = 0; rr < 4; rr++)
            #pragma unroll
            for (int kk = 0; kk < 8; kk++) s[rr][kk] = 0.f;

        #pragma unroll 2
        for (int d4 = 0; d4 < 16; d4++) {
            float4 q4[4];
            #pragma unroll
            for (int rr = 0; rr < 4; rr++)
                q4[rr] = *(const float4*)(Qs + (4*rg+rr)*PAD + 4*d4);
            const int swd = (d4 ^ kg) * 4;
            #pragma unroll
            for (int kk = 0; kk < 8; kk++) {
                float4 k4 = *(const float4*)(Ks + (8*kg+kk)*PAD + swd);
                #pragma unroll
                for (int rr = 0; rr < 4; rr++) {
                    s[rr][kk] += q4[rr].x*k4.x + q4[rr].y*k4.y
                               + q4[rr].z*k4.z + q4[rr].w*k4.w;
                }
            }
        }

        // online softmax per row; reduce across the 8 kg-lanes of this row group
        #pragma unroll
        for (int rr = 0; rr < 4; rr++) {
            float tm = s[rr][0];
            #pragma unroll
            for (int kk = 1; kk < 8; kk++) tm = fmaxf(tm, s[rr][kk]);
            tm = fmaxf(tm, __shfl_xor_sync(0xffffffffu, tm, 1));
            tm = fmaxf(tm, __shfl_xor_sync(0xffffffffu, tm, 2));
            tm = fmaxf(tm, __shfl_xor_sync(0xffffffffu, tm, 4));
            float mn = fmaxf(m[rr], tm);
            float a  = __expf(m[rr] - mn);
            float ts = 0.f;
            #pragma unroll
            for (int kk = 0; kk < 8; kk++) {
                float p = __expf(s[rr][kk] - mn);
                s[rr][kk] = p;
                ts += p;
            }
            ts += __shfl_xor_sync(0xffffffffu, ts, 1);
            ts += __shfl_xor_sync(0xffffffffu, ts, 2);
            ts += __shfl_xor_sync(0xffffffffu, ts, 4);
            m[rr] = mn;
            l[rr] = l[rr]*a + ts;
            #pragma unroll
            for (int c = 0; c < 8; c++) acc[rr*8+c] *= a;
        }

        // store P tile
        #pragma unroll
        for (int rr = 0; rr < 4; rr++) {
            float4 p0 = make_float4(s[rr][0], s[rr][1], s[rr][2], s[rr][3]);
            float4 p1 = make_float4(s[rr][4], s[rr][5], s[rr][6], s[rr][7]);
            *(float4*)(Ps + (4*rg+rr)*PAD + 8*kg)     = p0;
            *(float4*)(Ps + (4*rg+rr)*PAD + 8*kg + 4) = p1;
        }
        __syncthreads();

        // acc[rr][c] += sum_k P[4rg+rr][k] * V[k][8kg+c]
        #pragma unroll 2
        for (int k4 = 0; k4 < 16; k4++) {
            float4 p4[4];
            #pragma unroll
            for (int rr = 0; rr < 4; rr++)
                p4[rr] = *(const float4*)(Ps + (4*rg+rr)*PAD + 4*k4);
            #pragma unroll
            for (int kk = 0; kk < 4; kk++) {
                int k = 4*k4 + kk;
                float4 va = *(const float4*)(Vs + k*PAD + 8*kg);
                float4 vb = *(const float4*)(Vs + k*PAD + 8*kg + 4);
                #pragma unroll
                for (int rr = 0; rr < 4; rr++) {
                    float pv = (kk==0) ? p4[rr].x : (kk==1) ? p4[rr].y
                             : (kk==2) ? p4[rr].z : p4[rr].w;
                    acc[rr*8+0] += pv*va.x;
                    acc[rr*8+1] += pv*va.y;
                    acc[rr*8+2] += pv*va.z;
                    acc[rr*8+3] += pv*va.w;
                    acc[rr*8+4] += pv*vb.x;
                    acc[rr*8+5] += pv*vb.y;
                    acc[rr*8+6] += pv*vb.z;
                    acc[rr*8+7] += pv*vb.w;
                }
            }
        }
        __syncthreads();
    }

    // epilogue
    #pragma unroll
    for (int rr = 0; rr < 4; rr++) {
        const float inv = 1.f / l[rr];
        float* og = out + ((size_t)n*Ss + q0 + 4*rg + rr)*Dd + h*DH + 8*kg;
        float4 v0, v1;
        v0.x = acc[rr*8+0]*inv; v0.y = acc[rr*8+1]*inv;
        v0.z = acc[rr*8+2]*inv; v0.w = acc[rr*8+3]*inv;
        v1.x = acc[rr*8+4]*inv; v1.y = acc[rr*8+5]*inv;
        v1.z = acc[rr*8+6]*inv; v1.w = acc[rr*8+7]*inv;
        *(float4*)(og)     = v0;
        *(float4*)(og + 4) = v1;
    }
}

// ---------------------------------------------------------------------------
extern "C" void kernel_launch(void* const* d_in, const int* in_sizes, int n_in,
                              void* d_out, int out_size)
{
    const float* x  = (const float*)d_in[0];
    const float* Wq = (const float*)d_in[1];
    const float* bq = (const float*)d_in[2];
    const float* Wk = (const float*)d_in[3];
    const float* bk = (const float*)d_in[4];
    const float* Wv = (const float*)d_in[5];
    const float* bv = (const float*)d_in[6];
    float* out = (float*)d_out;

    const int smem = 4 * BQ * PAD * (int)sizeof(float);   // 69632 bytes
    cudaFuncSetAttribute(qkv_proj_kernel, cudaFuncAttributeMaxDynamicSharedMemorySize, smem);
    cudaFuncSetAttribute(attn_kernel,     cudaFuncAttributeMaxDynamicSharedMemorySize, smem);

    dim3 grid(Ss/BQ, Hh, Nn);   // (32, 16, 2)
    qkv_proj_kernel<<<grid, 256, smem>>>(x, Wq, bq, Wk, bk, Wv, bv);
    attn_kernel<<<grid, 128, smem>>>(out);
}

// round 4
// speedup vs baseline: 7.6836x; 4.0867x over previous
#include <cuda_runtime.h>
#include <cuda_fp16.h>
#include <stdint.h>
#include <math.h>

#define Nn 2
#define Ss 2048
#define Dd 1024
#define Hh 16
#define DH 64
#define BQ 128          // query rows per block (8 warps x 16)
#define BK 64           // keys per iteration
#define PAD 68          // fp32 smem pitch in proj kernel
#define KP 72           // half smem pitch for K / Vt tiles (bank-conflict-free fragments)

// QKV scratch, fp16. q pre-scaled by 1/sqrt(DH). v stored transposed per head.
__device__ __half g_q [(size_t)Nn*Hh*Ss*DH];
__device__ __half g_k [(size_t)Nn*Hh*Ss*DH];
__device__ __half g_vt[(size_t)Nn*Hh*DH*Ss];   // [n,h,d,s]

// ---------------------------------------------------------------------------
// Kernel 1: per-head QKV projection (fp32 compute, fp16 output).
// ---------------------------------------------------------------------------
__global__ void qkv_proj_kernel(const float* __restrict__ x,
                                const float* __restrict__ Wq, const float* __restrict__ bq,
                                const float* __restrict__ Wk, const float* __restrict__ bk,
                                const float* __restrict__ Wv, const float* __restrict__ bv)
{
    extern __shared__ float sm[];
    float* xs  = sm;                 // 64*PAD
    float* wqs = xs  + 64*PAD;
    float* wks = wqs + 64*PAD;
    float* wvs = wks + 64*PAD;

    const int s0  = blockIdx.x * 64;
    const int h   = blockIdx.y;
    const int n   = blockIdx.z;
    const int tid = threadIdx.x;

    const float* xg  = x  + ((size_t)(n*Ss + s0))*Dd + h*DH;
    const float* wqg = Wq + (size_t)h*DH*DH;
    const float* wkg = Wk + (size_t)h*DH*DH;
    const float* wvg = Wv + (size_t)h*DH*DH;

    #pragma unroll
    for (int it = 0; it < 4; it++) {
        int idx = tid + 256*it;          // float4 index, 0..1023
        int row = idx >> 4;
        int dd  = idx & 15;
        *(float4*)(xs  + row*PAD + 4*dd) = *(const float4*)(xg  + (size_t)row*Dd + 4*dd);
        *(float4*)(wqs + row*PAD + 4*dd) = *(const float4*)(wqg + row*DH + 4*dd);
        *(float4*)(wks + row*PAD + 4*dd) = *(const float4*)(wkg + row*DH + 4*dd);
        *(float4*)(wvs + row*PAD + 4*dd) = *(const float4*)(wvg + row*DH + 4*dd);
    }
    __syncthreads();

    const int r  = tid >> 2;
    const int t4 = tid & 3;

    float aq[16], ak[16], av[16];
    #pragma unroll
    for (int i = 0; i < 16; i++) {
        int e = t4 + 4*i;
        aq[i] = bq[h*DH + e];
        ak[i] = bk[h*DH + e];
        av[i] = bv[h*DH + e];
    }

    for (int d4 = 0; d4 < 16; d4++) {
        float4 x4 = *(const float4*)(xs + r*PAD + 4*d4);
        #pragma unroll
        for (int i = 0; i < 16; i++) {
            int e = t4 + 4*i;
            float4 w;
            w = *(const float4*)(wqs + e*PAD + 4*d4);
            aq[i] += x4.x*w.x + x4.y*w.y + x4.z*w.z + x4.w*w.w;
            w = *(const float4*)(wks + e*PAD + 4*d4);
            ak[i] += x4.x*w.x + x4.y*w.y + x4.z*w.z + x4.w*w.w;
            w = *(const float4*)(wvs + e*PAD + 4*d4);
            av[i] += x4.x*w.x + x4.y*w.y + x4.z*w.z + x4.w*w.w;
        }
    }

    const size_t base   = ((size_t)((n*Hh + h))*Ss + s0 + r)*DH;
    const size_t vtbase = ((size_t)(n*Hh + h))*DH*Ss;
    #pragma unroll
    for (int i = 0; i < 16; i++) {
        int e = t4 + 4*i;
        g_q [base + e] = __float2half_rn(aq[i] * 0.125f);   // fold 1/sqrt(DH)
        g_k [base + e] = __float2half_rn(ak[i]);
        g_vt[vtbase + (size_t)e*Ss + s0 + r] = __float2half_rn(av[i]);
    }
}

// ---------------------------------------------------------------------------
// fp16 tensor-core flash attention.
// ---------------------------------------------------------------------------
__device__ __forceinline__ void mma16816(float c[4],
                                         uint32_t a0, uint32_t a1, uint32_t a2, uint32_t a3,
                                         uint32_t b0, uint32_t b1)
{
    asm volatile(
        "mma.sync.aligned.m16n8k16.row.col.f32.f16.f16.f32 "
        "{%0,%1,%2,%3}, {%4,%5,%6,%7}, {%8,%9}, {%0,%1,%2,%3};\n"
        : "+f"(c[0]), "+f"(c[1]), "+f"(c[2]), "+f"(c[3])
        : "r"(a0), "r"(a1), "r"(a2), "r"(a3), "r"(b0), "r"(b1));
}

__device__ __forceinline__ uint32_t packh2(float a, float b)
{
    __half2 h = __floats2half2_rn(a, b);
    return *reinterpret_cast<uint32_t*>(&h);
}

__global__ void __launch_bounds__(256) attn_kernel(float* __restrict__ out)
{
    __shared__ __half Ks [BK*KP];   // [key][d]  pitch 72
    __shared__ __half Vts[DH*KP];   // [d][key]  pitch 72

    const int q0   = blockIdx.x * BQ;
    const int h    = blockIdx.y;
    const int n    = blockIdx.z;
    const int tid  = threadIdx.x;
    const int warp = tid >> 5;
    const int lane = tid & 31;
    const int g    = lane >> 2;     // row group 0..7
    const int t    = lane & 3;

    const size_t head_off = (size_t)(n*Hh + h) * Ss * DH;
    const __half* qg  = g_q  + head_off;
    const __half* kg  = g_k  + head_off;
    const __half* vtg = g_vt + head_off;   // [d][s]

    // Q fragments, resident for whole kernel (already scaled by 0.125).
    const int rlo = q0 + warp*16 + g;
    const __half* q_lo = qg + (size_t)rlo*DH;
    const __half* q_hi = q_lo + 8*DH;
    uint32_t qa[4][4];
    #pragma unroll
    for (int s = 0; s < 4; s++) {
        qa[s][0] = *(const uint32_t*)(q_lo + 16*s + 2*t);
        qa[s][1] = *(const uint32_t*)(q_hi + 16*s + 2*t);
        qa[s][2] = *(const uint32_t*)(q_lo + 16*s + 8 + 2*t);
        qa[s][3] = *(const uint32_t*)(q_hi + 16*s + 8 + 2*t);
    }

    float o[8][4];
    #pragma unroll
    for (int j = 0; j < 8; j++)
        #pragma unroll
        for (int i = 0; i < 4; i++) o[j][i] = 0.f;
    float m_lo = -1e30f, m_hi = -1e30f, l_lo = 0.f, l_hi = 0.f;

    for (int k0 = 0; k0 < Ss; k0 += BK) {
        __syncthreads();
        // cooperative loads: K tile [64 keys][64 d], Vt tile [64 d][64 keys]
        #pragma unroll
        for (int it = 0; it < 2; it++) {
            int idx = tid + 256*it;          // 0..511 float4 slots
            int row = idx >> 3, c = idx & 7; // 8 chunks of 8 halves per row
            *(float4*)(Ks  + row*KP + 8*c) = *(const float4*)(kg  + (size_t)(k0+row)*DH + 8*c);
            *(float4*)(Vts + row*KP + 8*c) = *(const float4*)(vtg + (size_t)row*Ss + k0 + 8*c);
        }
        __syncthreads();

        // S = Q K^T : c[j] = 16x8 tile over keys 8j..8j+7
        float c[8][4];
        #pragma unroll
        for (int j = 0; j < 8; j++) {
            c[j][0] = c[j][1] = c[j][2] = c[j][3] = 0.f;
            #pragma unroll
            for (int s = 0; s < 4; s++) {
                const __half* kb = Ks + (8*j + g)*KP + 16*s + 2*t;
                uint32_t b0 = *(const uint32_t*)(kb);
                uint32_t b1 = *(const uint32_t*)(kb + 8);
                mma16816(c[j], qa[s][0], qa[s][1], qa[s][2], qa[s][3], b0, b1);
            }
        }

        // online softmax (rows g and g+8 of this warp's 16-row strip)
        float tm_lo = c[0][0], tm_hi = c[0][2];
        #pragma unroll
        for (int j = 0; j < 8; j++) {
            tm_lo = fmaxf(tm_lo, fmaxf(c[j][0], c[j][1]));
            tm_hi = fmaxf(tm_hi, fmaxf(c[j][2], c[j][3]));
        }
        tm_lo = fmaxf(tm_lo, __shfl_xor_sync(0xffffffffu, tm_lo, 1));
        tm_lo = fmaxf(tm_lo, __shfl_xor_sync(0xffffffffu, tm_lo, 2));
        tm_hi = fmaxf(tm_hi, __shfl_xor_sync(0xffffffffu, tm_hi, 1));
        tm_hi = fmaxf(tm_hi, __shfl_xor_sync(0xffffffffu, tm_hi, 2));

        float mn_lo = fmaxf(m_lo, tm_lo);
        float mn_hi = fmaxf(m_hi, tm_hi);
        float al_lo = __expf(m_lo - mn_lo);
        float al_hi = __expf(m_hi - mn_hi);

        float ts_lo = 0.f, ts_hi = 0.f;
        #pragma unroll
        for (int j = 0; j < 8; j++) {
            c[j][0] = __expf(c[j][0] - mn_lo);
            c[j][1] = __expf(c[j][1] - mn_lo);
            c[j][2] = __expf(c[j][2] - mn_hi);
            c[j][3] = __expf(c[j][3] - mn_hi);
            ts_lo += c[j][0] + c[j][1];
            ts_hi += c[j][2] + c[j][3];
        }
        ts_lo += __shfl_xor_sync(0xffffffffu, ts_lo, 1);
        ts_lo += __shfl_xor_sync(0xffffffffu, ts_lo, 2);
        ts_hi += __shfl_xor_sync(0xffffffffu, ts_hi, 1);
        ts_hi += __shfl_xor_sync(0xffffffffu, ts_hi, 2);

        m_lo = mn_lo; m_hi = mn_hi;
        l_lo = l_lo*al_lo + ts_lo;
        l_hi = l_hi*al_hi + ts_hi;

        #pragma unroll
        for (int j = 0; j < 8; j++) {
            o[j][0] *= al_lo; o[j][1] *= al_lo;
            o[j][2] *= al_hi; o[j][3] *= al_hi;
        }

        // O += P V : A = packed score fragments, B from Vt
        #pragma unroll
        for (int s = 0; s < 4; s++) {
            uint32_t a0 = packh2(c[2*s  ][0], c[2*s  ][1]);
            uint32_t a1 = packh2(c[2*s  ][2], c[2*s  ][3]);
            uint32_t a2 = packh2(c[2*s+1][0], c[2*s+1][1]);
            uint32_t a3 = packh2(c[2*s+1][2], c[2*s+1][3]);
            #pragma unroll
            for (int jv = 0; jv < 8; jv++) {
                const __half* vb = Vts + (8*jv + g)*KP + 16*s + 2*t;
                uint32_t b0 = *(const uint32_t*)(vb);
                uint32_t b1 = *(const uint32_t*)(vb + 8);
                mma16816(o[jv], a0, a1, a2, a3, b0, b1);
            }
        }
    }

    // epilogue
    const float inv_lo = 1.f / l_lo;
    const float inv_hi = 1.f / l_hi;
    float* out_lo = out + ((size_t)n*Ss + rlo    )*Dd + h*DH;
    float* out_hi = out + ((size_t)n*Ss + rlo + 8)*Dd + h*DH;
    #pragma unroll
    for (int jv = 0; jv < 8; jv++) {
        float2 vlo = make_float2(o[jv][0]*inv_lo, o[jv][1]*inv_lo);
        float2 vhi = make_float2(o[jv][2]*inv_hi, o[jv][3]*inv_hi);
        *(float2*)(out_lo + 8*jv + 2*t) = vlo;
        *(float2*)(out_hi + 8*jv + 2*t) = vhi;
    }
}

// ---------------------------------------------------------------------------
extern "C" void kernel_launch(void* const* d_in, const int* in_sizes, int n_in,
                              void* d_out, int out_size)
{
    const float* x  = (const float*)d_in[0];
    const float* Wq = (const float*)d_in[1];
    const float* bq = (const float*)d_in[2];
    const float* Wk = (const float*)d_in[3];
    const float* bk = (const float*)d_in[4];
    const float* Wv = (const float*)d_in[5];
    const float* bv = (const float*)d_in[6];
    float* out = (float*)d_out;

    const int smem = 4 * 64 * PAD * (int)sizeof(float);   // 69632 bytes
    cudaFuncSetAttribute(qkv_proj_kernel, cudaFuncAttributeMaxDynamicSharedMemorySize, smem);

    dim3 pgrid(Ss/64, Hh, Nn);   // (32, 16, 2)
    qkv_proj_kernel<<<pgrid, 256, smem>>>(x, Wq, bq, Wk, bk, Wv, bv);

    dim3 agrid(Ss/BQ, Hh, Nn);   // (16, 16, 2)
    attn_kernel<<<agrid, 256>>>(out);
}

// round 5
// speedup vs baseline: 12.7984x; 1.6657x over previous
#include <cuda_runtime.h>
#include <cuda_fp16.h>
#include <stdint.h>
#include <math.h>

#define Nn 2
#define Ss 2048
#define Dd 1024
#define Hh 16
#define DH 64
#define BQ 128          // attn: query rows per block (8 warps x 16)
#define BK 64           // attn: keys per iteration
#define KP 72           // half smem pitch (bank-conflict-free fragments)

// QKV scratch, fp16. q pre-scaled by 1/sqrt(DH). v stored transposed per head.
__device__ __half g_q [(size_t)Nn*Hh*Ss*DH];
__device__ __half g_k [(size_t)Nn*Hh*Ss*DH];
__device__ __half g_vt[(size_t)Nn*Hh*DH*Ss];   // [n,h,d,s]

__device__ __forceinline__ void mma16816(float c[4],
                                         uint32_t a0, uint32_t a1, uint32_t a2, uint32_t a3,
                                         uint32_t b0, uint32_t b1)
{
    asm volatile(
        "mma.sync.aligned.m16n8k16.row.col.f32.f16.f16.f32 "
        "{%0,%1,%2,%3}, {%4,%5,%6,%7}, {%8,%9}, {%0,%1,%2,%3};\n"
        : "+f"(c[0]), "+f"(c[1]), "+f"(c[2]), "+f"(c[3])
        : "r"(a0), "r"(a1), "r"(a2), "r"(a3), "r"(b0), "r"(b1));
}

__device__ __forceinline__ uint32_t packh2(float a, float b)
{
    __half2 h = __floats2half2_rn(a, b);
    return *reinterpret_cast<uint32_t*>(&h);
}

#define CP_ASYNC16(dst, src) \
    asm volatile("cp.async.cg.shared.global [%0], [%1], 16;\n" :: "r"(dst), "l"(src))
#define CP_COMMIT() asm volatile("cp.async.commit_group;\n")
#define CP_WAIT(n)  asm volatile("cp.async.wait_group %0;\n" :: "n"(n))

// ---------------------------------------------------------------------------
// Kernel 1: per-head QKV projection, fp16 tensor cores.
// Block = 64 seq rows x 1 head x 1 batch, 128 threads (4 warps x 16 rows).
// ---------------------------------------------------------------------------
__global__ void __launch_bounds__(128) qkv_proj_kernel(
        const float* __restrict__ x,
        const float* __restrict__ Wq, const float* __restrict__ bq,
        const float* __restrict__ Wk, const float* __restrict__ bk,
        const float* __restrict__ Wv, const float* __restrict__ bv)
{
    __shared__ __half xs[64*KP];
    __shared__ __half ws[3][64*KP];
    __shared__ __half vs[64*KP];

    const int s0  = blockIdx.x * 64;
    const int h   = blockIdx.y;
    const int n   = blockIdx.z;
    const int tid = threadIdx.x;
    const int warp = tid >> 5;
    const int lane = tid & 31;
    const int g    = lane >> 2;
    const int t    = lane & 3;

    const float* xg = x + ((size_t)(n*Ss + s0))*Dd + h*DH;
    const float* wg[3] = { Wq + (size_t)h*DH*DH, Wk + (size_t)h*DH*DH, Wv + (size_t)h*DH*DH };
    const float* bg[3] = { bq + h*DH, bk + h*DH, bv + h*DH };

    // load + fp16-convert x tile and the three weight tiles
    #pragma unroll
    for (int it = 0; it < 8; it++) {
        int idx = tid + 128*it;          // float4 slot, 0..1023
        int row = idx >> 4, dd = idx & 15;
        float4 v = *(const float4*)(xg + (size_t)row*Dd + 4*dd);
        *(uint32_t*)(xs + row*KP + 4*dd)     = packh2(v.x, v.y);
        *(uint32_t*)(xs + row*KP + 4*dd + 2) = packh2(v.z, v.w);
        #pragma unroll
        for (int mt = 0; mt < 3; mt++) {
            float4 w = *(const float4*)(wg[mt] + row*DH + 4*dd);
            *(uint32_t*)(ws[mt] + row*KP + 4*dd)     = packh2(w.x, w.y);
            *(uint32_t*)(ws[mt] + row*KP + 4*dd + 2) = packh2(w.z, w.w);
        }
    }
    __syncthreads();

    // A fragments: 16 rows of this warp
    const int r = 16*warp + g;
    uint32_t qa[4][4];
    #pragma unroll
    for (int s = 0; s < 4; s++) {
        qa[s][0] = *(const uint32_t*)(xs + r*KP + 16*s + 2*t);
        qa[s][1] = *(const uint32_t*)(xs + (r+8)*KP + 16*s + 2*t);
        qa[s][2] = *(const uint32_t*)(xs + r*KP + 16*s + 8 + 2*t);
        qa[s][3] = *(const uint32_t*)(xs + (r+8)*KP + 16*s + 8 + 2*t);
    }

    const size_t base   = ((size_t)((n*Hh + h))*Ss + s0)*DH;
    const size_t vtbase = ((size_t)(n*Hh + h))*DH*Ss;

    #pragma unroll
    for (int mt = 0; mt < 3; mt++) {
        float c[8][4];
        #pragma unroll
        for (int j = 0; j < 8; j++) c[j][0] = c[j][1] = c[j][2] = c[j][3] = 0.f;
        #pragma unroll
        for (int j = 0; j < 8; j++) {
            #pragma unroll
            for (int s = 0; s < 4; s++) {
                const __half* wb = ws[mt] + (8*j + g)*KP + 16*s + 2*t;
                uint32_t b0 = *(const uint32_t*)(wb);
                uint32_t b1 = *(const uint32_t*)(wb + 8);
                mma16816(c[j], qa[s][0], qa[s][1], qa[s][2], qa[s][3], b0, b1);
            }
        }
        // bias + store
        #pragma unroll
        for (int j = 0; j < 8; j++) {
            float b0 = bg[mt][8*j + 2*t];
            float b1 = bg[mt][8*j + 2*t + 1];
            float c0 = c[j][0] + b0, c1 = c[j][1] + b1;   // row r
            float c2 = c[j][2] + b0, c3 = c[j][3] + b1;   // row r+8
            if (mt == 0) {
                *(uint32_t*)(g_q + base + (size_t)r*DH     + 8*j + 2*t) = packh2(c0*0.125f, c1*0.125f);
                *(uint32_t*)(g_q + base + (size_t)(r+8)*DH + 8*j + 2*t) = packh2(c2*0.125f, c3*0.125f);
            } else if (mt == 1) {
                *(uint32_t*)(g_k + base + (size_t)r*DH     + 8*j + 2*t) = packh2(c0, c1);
                *(uint32_t*)(g_k + base + (size_t)(r+8)*DH + 8*j + 2*t) = packh2(c2, c3);
            } else {
                *(uint32_t*)(vs + r*KP     + 8*j + 2*t) = packh2(c0, c1);
                *(uint32_t*)(vs + (r+8)*KP + 8*j + 2*t) = packh2(c2, c3);
            }
        }
    }
    __syncthreads();

    // transposed, coalesced store of v: g_vt[e][s0+s]
    #pragma unroll
    for (int it = 0; it < 4; it++) {
        int idx = tid + 128*it;          // 0..511 float4 slots
        int e = idx >> 3, cch = idx & 7; // 8 chunks of 8 halves along s
        __half tmp[8];
        #pragma unroll
        for (int i = 0; i < 8; i++) tmp[i] = vs[(8*cch + i)*KP + e];
        *(float4*)(g_vt + vtbase + (size_t)e*Ss + s0 + 8*cch) = *(float4*)tmp;
    }
}

// ---------------------------------------------------------------------------
// Kernel 2: fp16 tensor-core flash attention with cp.async double buffering.
// ---------------------------------------------------------------------------
__global__ void __launch_bounds__(256) attn_kernel(float* __restrict__ out)
{
    __shared__ __half Ks [2][BK*KP];   // [key][d]
    __shared__ __half Vts[2][DH*KP];   // [d][key]

    const int q0   = blockIdx.x * BQ;
    const int h    = blockIdx.y;
    const int n    = blockIdx.z;
    const int tid  = threadIdx.x;
    const int warp = tid >> 5;
    const int lane = tid & 31;
    const int g    = lane >> 2;
    const int t    = lane & 3;

    const size_t head_off = (size_t)(n*Hh + h) * Ss * DH;
    const __half* qg  = g_q  + head_off;
    const __half* kg  = g_k  + head_off;
    const __half* vtg = g_vt + head_off;

    const uint32_t sKs  = (uint32_t)__cvta_generic_to_shared(&Ks[0][0]);
    const uint32_t sVts = (uint32_t)__cvta_generic_to_shared(&Vts[0][0]);

    // Q fragments, register resident (pre-scaled by 0.125)
    const int rlo = q0 + warp*16 + g;
    const __half* q_lo = qg + (size_t)rlo*DH;
    const __half* q_hi = q_lo + 8*DH;
    uint32_t qa[4][4];
    #pragma unroll
    for (int s = 0; s < 4; s++) {
        qa[s][0] = *(const uint32_t*)(q_lo + 16*s + 2*t);
        qa[s][1] = *(const uint32_t*)(q_hi + 16*s + 2*t);
        qa[s][2] = *(const uint32_t*)(q_lo + 16*s + 8 + 2*t);
        qa[s][3] = *(const uint32_t*)(q_hi + 16*s + 8 + 2*t);
    }

    float o[8][4];
    #pragma unroll
    for (int j = 0; j < 8; j++)
        #pragma unroll
        for (int i = 0; i < 4; i++) o[j][i] = 0.f;
    float m_lo = -1e30f, m_hi = -1e30f, l_lo = 0.f, l_hi = 0.f;

    // tile loader: 4 cp.async.16 per thread (Ks: 2 slots, Vts: 2 slots)
    auto load_tiles = [&](int buf, int k0) {
        #pragma unroll
        for (int it = 0; it < 2; it++) {
            int idx = tid + 256*it;          // 0..511
            int row = idx >> 3, c = idx & 7;
            CP_ASYNC16(sKs  + (uint32_t)((buf*BK*KP + row*KP + 8*c)*sizeof(__half)),
                       kg  + (size_t)(k0+row)*DH + 8*c);
            CP_ASYNC16(sVts + (uint32_t)((buf*DH*KP + row*KP + 8*c)*sizeof(__half)),
                       vtg + (size_t)row*Ss + k0 + 8*c);
        }
    };

    load_tiles(0, 0);
    CP_COMMIT();

    const int NT = Ss / BK;   // 32
    for (int it = 0; it < NT; it++) {
        const int cur = it & 1;
        if (it + 1 < NT) {
            load_tiles(1 - cur, (it + 1) * BK);
            CP_COMMIT();
            CP_WAIT(1);
        } else {
            CP_WAIT(0);
        }
        __syncthreads();

        const __half* ksb = Ks[cur];
        const __half* vtb = Vts[cur];

        // S = Q K^T
        float c[8][4];
        #pragma unroll
        for (int j = 0; j < 8; j++) {
            c[j][0] = c[j][1] = c[j][2] = c[j][3] = 0.f;
            #pragma unroll
            for (int s = 0; s < 4; s++) {
                const __half* kb = ksb + (8*j + g)*KP + 16*s + 2*t;
                uint32_t b0 = *(const uint32_t*)(kb);
                uint32_t b1 = *(const uint32_t*)(kb + 8);
                mma16816(c[j], qa[s][0], qa[s][1], qa[s][2], qa[s][3], b0, b1);
            }
        }

        // online softmax
        float tm_lo = c[0][0], tm_hi = c[0][2];
        #pragma unroll
        for (int j = 0; j < 8; j++) {
            tm_lo = fmaxf(tm_lo, fmaxf(c[j][0], c[j][1]));
            tm_hi = fmaxf(tm_hi, fmaxf(c[j][2], c[j][3]));
        }
        tm_lo = fmaxf(tm_lo, __shfl_xor_sync(0xffffffffu, tm_lo, 1));
        tm_lo = fmaxf(tm_lo, __shfl_xor_sync(0xffffffffu, tm_lo, 2));
        tm_hi = fmaxf(tm_hi, __shfl_xor_sync(0xffffffffu, tm_hi, 1));
        tm_hi = fmaxf(tm_hi, __shfl_xor_sync(0xffffffffu, tm_hi, 2));

        float mn_lo = fmaxf(m_lo, tm_lo);
        float mn_hi = fmaxf(m_hi, tm_hi);
        float al_lo = __expf(m_lo - mn_lo);
        float al_hi = __expf(m_hi - mn_hi);

        float ts_lo = 0.f, ts_hi = 0.f;
        #pragma unroll
        for (int j = 0; j < 8; j++) {
            c[j][0] = __expf(c[j][0] - mn_lo);
            c[j][1] = __expf(c[j][1] - mn_lo);
            c[j][2] = __expf(c[j][2] - mn_hi);
            c[j][3] = __expf(c[j][3] - mn_hi);
            ts_lo += c[j][0] + c[j][1];
            ts_hi += c[j][2] + c[j][3];
        }
        ts_lo += __shfl_xor_sync(0xffffffffu, ts_lo, 1);
        ts_lo += __shfl_xor_sync(0xffffffffu, ts_lo, 2);
        ts_hi += __shfl_xor_sync(0xffffffffu, ts_hi, 1);
        ts_hi += __shfl_xor_sync(0xffffffffu, ts_hi, 2);

        m_lo = mn_lo; m_hi = mn_hi;
        l_lo = l_lo*al_lo + ts_lo;
        l_hi = l_hi*al_hi + ts_hi;

        #pragma unroll
        for (int j = 0; j < 8; j++) {
            o[j][0] *= al_lo; o[j][1] *= al_lo;
            o[j][2] *= al_hi; o[j][3] *= al_hi;
        }

        // O += P V
        #pragma unroll
        for (int s = 0; s < 4; s++) {
            uint32_t a0 = packh2(c[2*s  ][0], c[2*s  ][1]);
            uint32_t a1 = packh2(c[2*s  ][2], c[2*s  ][3]);
            uint32_t a2 = packh2(c[2*s+1][0], c[2*s+1][1]);
            uint32_t a3 = packh2(c[2*s+1][2], c[2*s+1][3]);
            #pragma unroll
            for (int jv = 0; jv < 8; jv++) {
                const __half* vb = vtb + (8*jv + g)*KP + 16*s + 2*t;
                uint32_t b0 = *(const uint32_t*)(vb);
                uint32_t b1 = *(const uint32_t*)(vb + 8);
                mma16816(o[jv], a0, a1, a2, a3, b0, b1);
            }
        }
        __syncthreads();   // protect buffer reuse by next iteration's cp.async
    }

    // epilogue
    const float inv_lo = 1.f / l_lo;
    const float inv_hi = 1.f / l_hi;
    float* out_lo = out + ((size_t)n*Ss + rlo    )*Dd + h*DH;
    float* out_hi = out + ((size_t)n*Ss + rlo + 8)*Dd + h*DH;
    #pragma unroll
    for (int jv = 0; jv < 8; jv++) {
        float2 vlo = make_float2(o[jv][0]*inv_lo, o[jv][1]*inv_lo);
        float2 vhi = make_float2(o[jv][2]*inv_hi, o[jv][3]*inv_hi);
        *(float2*)(out_lo + 8*jv + 2*t) = vlo;
        *(float2*)(out_hi + 8*jv + 2*t) = vhi;
    }
}

// ---------------------------------------------------------------------------
extern "C" void kernel_launch(void* const* d_in, const int* in_sizes, int n_in,
                              void* d_out, int out_size)
{
    const float* x  = (const float*)d_in[0];
    const float* Wq = (const float*)d_in[1];
    const float* bq = (const float*)d_in[2];
    const float* Wk = (const float*)d_in[3];
    const float* bk = (const float*)d_in[4];
    const float* Wv = (const float*)d_in[5];
    const float* bv = (const float*)d_in[6];
    float* out = (float*)d_out;

    dim3 pgrid(Ss/64, Hh, Nn);   // (32, 16, 2)
    qkv_proj_kernel<<<pgrid, 128>>>(x, Wq, bq, Wk, bk, Wv, bv);

    dim3 agrid(Ss/BQ, Hh, Nn);   // (16, 16, 2)
    attn_kernel<<<agrid, 256>>>(out);
}

// round 6
// speedup vs baseline: 13.4572x; 1.0515x over previous
#include <cuda_runtime.h>
#include <cuda_fp16.h>
#include <stdint.h>
#include <math.h>

#define Nn 2
#define Ss 2048
#define Dd 1024
#define Hh 16
#define DH 64
#define BQ 128          // attn: query rows per block (8 warps x 16)
#define BK 64           // attn: keys per iteration
#define KP 72           // half smem pitch (bank-conflict-free fragments)

// Q pre-scale: (1/sqrt(DH)) * log2(e), so scores are in log2 domain for ex2.
#define QSCALE 0.18033688011112042f

// QKV scratch, fp16. v stored transposed per head.
__device__ __half g_q [(size_t)Nn*Hh*Ss*DH];
__device__ __half g_k [(size_t)Nn*Hh*Ss*DH];
__device__ __half g_vt[(size_t)Nn*Hh*DH*Ss];   // [n,h,d,s]

__device__ __forceinline__ void mma16816(float c[4],
                                         uint32_t a0, uint32_t a1, uint32_t a2, uint32_t a3,
                                         uint32_t b0, uint32_t b1)
{
    asm volatile(
        "mma.sync.aligned.m16n8k16.row.col.f32.f16.f16.f32 "
        "{%0,%1,%2,%3}, {%4,%5,%6,%7}, {%8,%9}, {%0,%1,%2,%3};\n"
        : "+f"(c[0]), "+f"(c[1]), "+f"(c[2]), "+f"(c[3])
        : "r"(a0), "r"(a1), "r"(a2), "r"(a3), "r"(b0), "r"(b1));
}

__device__ __forceinline__ uint32_t packh2(float a, float b)
{
    __half2 h = __floats2half2_rn(a, b);
    return *reinterpret_cast<uint32_t*>(&h);
}

__device__ __forceinline__ float ex2f(float x)
{
    float r;
    asm volatile("ex2.approx.f32 %0, %1;\n" : "=f"(r) : "f"(x));
    return r;
}

#define CP_ASYNC16(dst, src) \
    asm volatile("cp.async.cg.shared.global [%0], [%1], 16;\n" :: "r"(dst), "l"(src))
#define CP_COMMIT() asm volatile("cp.async.commit_group;\n")
#define CP_WAIT(n)  asm volatile("cp.async.wait_group %0;\n" :: "n"(n))

// ---------------------------------------------------------------------------
// Kernel 1: per-head QKV projection, fp16 tensor cores.
// ---------------------------------------------------------------------------
__global__ void __launch_bounds__(128) qkv_proj_kernel(
        const float* __restrict__ x,
        const float* __restrict__ Wq, const float* __restrict__ bq,
        const float* __restrict__ Wk, const float* __restrict__ bk,
        const float* __restrict__ Wv, const float* __restrict__ bv)
{
    __shared__ __half xs[64*KP];
    __shared__ __half ws[3][64*KP];
    __shared__ __half vs[64*KP];

    const int s0  = blockIdx.x * 64;
    const int h   = blockIdx.y;
    const int n   = blockIdx.z;
    const int tid = threadIdx.x;
    const int warp = tid >> 5;
    const int lane = tid & 31;
    const int g    = lane >> 2;
    const int t    = lane & 3;

    const float* xg = x + ((size_t)(n*Ss + s0))*Dd + h*DH;
    const float* wg[3] = { Wq + (size_t)h*DH*DH, Wk + (size_t)h*DH*DH, Wv + (size_t)h*DH*DH };
    const float* bg[3] = { bq + h*DH, bk + h*DH, bv + h*DH };

    #pragma unroll
    for (int it = 0; it < 8; it++) {
        int idx = tid + 128*it;
        int row = idx >> 4, dd = idx & 15;
        float4 v = *(const float4*)(xg + (size_t)row*Dd + 4*dd);
        *(uint32_t*)(xs + row*KP + 4*dd)     = packh2(v.x, v.y);
        *(uint32_t*)(xs + row*KP + 4*dd + 2) = packh2(v.z, v.w);
        #pragma unroll
        for (int mt = 0; mt < 3; mt++) {
            float4 w = *(const float4*)(wg[mt] + row*DH + 4*dd);
            *(uint32_t*)(ws[mt] + row*KP + 4*dd)     = packh2(w.x, w.y);
            *(uint32_t*)(ws[mt] + row*KP + 4*dd + 2) = packh2(w.z, w.w);
        }
    }
    __syncthreads();

    const int r = 16*warp + g;
    uint32_t qa[4][4];
    #pragma unroll
    for (int s = 0; s < 4; s++) {
        qa[s][0] = *(const uint32_t*)(xs + r*KP + 16*s + 2*t);
        qa[s][1] = *(const uint32_t*)(xs + (r+8)*KP + 16*s + 2*t);
        qa[s][2] = *(const uint32_t*)(xs + r*KP + 16*s + 8 + 2*t);
        qa[s][3] = *(const uint32_t*)(xs + (r+8)*KP + 16*s + 8 + 2*t);
    }

    const size_t base   = ((size_t)((n*Hh + h))*Ss + s0)*DH;
    const size_t vtbase = ((size_t)(n*Hh + h))*DH*Ss;

    #pragma unroll
    for (int mt = 0; mt < 3; mt++) {
        float c[8][4];
        #pragma unroll
        for (int j = 0; j < 8; j++) c[j][0] = c[j][1] = c[j][2] = c[j][3] = 0.f;
        #pragma unroll
        for (int j = 0; j < 8; j++) {
            #pragma unroll
            for (int s = 0; s < 4; s++) {
                const __half* wb = ws[mt] + (8*j + g)*KP + 16*s + 2*t;
                uint32_t b0 = *(const uint32_t*)(wb);
                uint32_t b1 = *(const uint32_t*)(wb + 8);
                mma16816(c[j], qa[s][0], qa[s][1], qa[s][2], qa[s][3], b0, b1);
            }
        }
        #pragma unroll
        for (int j = 0; j < 8; j++) {
            float b0 = bg[mt][8*j + 2*t];
            float b1 = bg[mt][8*j + 2*t + 1];
            float c0 = c[j][0] + b0, c1 = c[j][1] + b1;
            float c2 = c[j][2] + b0, c3 = c[j][3] + b1;
            if (mt == 0) {
                *(uint32_t*)(g_q + base + (size_t)r*DH     + 8*j + 2*t) = packh2(c0*QSCALE, c1*QSCALE);
                *(uint32_t*)(g_q + base + (size_t)(r+8)*DH + 8*j + 2*t) = packh2(c2*QSCALE, c3*QSCALE);
            } else if (mt == 1) {
                *(uint32_t*)(g_k + base + (size_t)r*DH     + 8*j + 2*t) = packh2(c0, c1);
                *(uint32_t*)(g_k + base + (size_t)(r+8)*DH + 8*j + 2*t) = packh2(c2, c3);
            } else {
                *(uint32_t*)(vs + r*KP     + 8*j + 2*t) = packh2(c0, c1);
                *(uint32_t*)(vs + (r+8)*KP + 8*j + 2*t) = packh2(c2, c3);
            }
        }
    }
    __syncthreads();

    #pragma unroll
    for (int it = 0; it < 4; it++) {
        int idx = tid + 128*it;
        int e = idx >> 3, cch = idx & 7;
        __half tmp[8];
        #pragma unroll
        for (int i = 0; i < 8; i++) tmp[i] = vs[(8*cch + i)*KP + e];
        *(float4*)(g_vt + vtbase + (size_t)e*Ss + s0 + 8*cch) = *(float4*)tmp;
    }
}

// ---------------------------------------------------------------------------
// Kernel 2: fp16 tensor-core flash attention. Scores in log2 domain (ex2).
// Row-sum l accumulated by tensor core via an all-ones B fragment.
// ---------------------------------------------------------------------------
__global__ void __launch_bounds__(256) attn_kernel(float* __restrict__ out)
{
    __shared__ __half Ks [2][BK*KP];   // [key][d]
    __shared__ __half Vts[2][DH*KP];   // [d][key]

    const int q0   = blockIdx.x * BQ;
    const int h    = blockIdx.y;
    const int n    = blockIdx.z;
    const int tid  = threadIdx.x;
    const int warp = tid >> 5;
    const int lane = tid & 31;
    const int g    = lane >> 2;
    const int t    = lane & 3;

    const size_t head_off = (size_t)(n*Hh + h) * Ss * DH;
    const __half* qg  = g_q  + head_off;
    const __half* kg  = g_k  + head_off;
    const __half* vtg = g_vt + head_off;

    const uint32_t sKs  = (uint32_t)__cvta_generic_to_shared(&Ks[0][0]);
    const uint32_t sVts = (uint32_t)__cvta_generic_to_shared(&Vts[0][0]);

    // Q fragments (pre-scaled by 0.125*log2e)
    const int rlo = q0 + warp*16 + g;
    const __half* q_lo = qg + (size_t)rlo*DH;
    const __half* q_hi = q_lo + 8*DH;
    uint32_t qa[4][4];
    #pragma unroll
    for (int s = 0; s < 4; s++) {
        qa[s][0] = *(const uint32_t*)(q_lo + 16*s + 2*t);
        qa[s][1] = *(const uint32_t*)(q_hi + 16*s + 2*t);
        qa[s][2] = *(const uint32_t*)(q_lo + 16*s + 8 + 2*t);
        qa[s][3] = *(const uint32_t*)(q_hi + 16*s + 8 + 2*t);
    }

    float o[8][4];
    #pragma unroll
    for (int j = 0; j < 8; j++)
        #pragma unroll
        for (int i = 0; i < 4; i++) o[j][i] = 0.f;
    float lacc[4] = {0.f, 0.f, 0.f, 0.f};   // row-sum accumulator (ones-B MMA)
    float m_lo = -1e30f, m_hi = -1e30f;
    const uint32_t ONES = 0x3C003C00u;       // half2(1,1)

    auto load_tiles = [&](int buf, int k0) {
        #pragma unroll
        for (int it = 0; it < 2; it++) {
            int idx = tid + 256*it;
            int row = idx >> 3, c = idx & 7;
            CP_ASYNC16(sKs  + (uint32_t)((buf*BK*KP + row*KP + 8*c)*sizeof(__half)),
                       kg  + (size_t)(k0+row)*DH + 8*c);
            CP_ASYNC16(sVts + (uint32_t)((buf*DH*KP + row*KP + 8*c)*sizeof(__half)),
                       vtg + (size_t)row*Ss + k0 + 8*c);
        }
    };

    load_tiles(0, 0);
    CP_COMMIT();

    const int NT = Ss / BK;   // 32
    for (int it = 0; it < NT; it++) {
        const int cur = it & 1;
        CP_WAIT(0);
        __syncthreads();               // cur's data visible; 1-cur fully consumed
        if (it + 1 < NT) {
            load_tiles(1 - cur, (it + 1) * BK);
            CP_COMMIT();
        }

        const __half* ksb = Ks[cur];
        const __half* vtb = Vts[cur];

        // S = Q K^T (log2 domain)
        float c[8][4];
        #pragma unroll
        for (int j = 0; j < 8; j++) {
            c[j][0] = c[j][1] = c[j][2] = c[j][3] = 0.f;
            #pragma unroll
            for (int s = 0; s < 4; s++) {
                const __half* kb = ksb + (8*j + g)*KP + 16*s + 2*t;
                uint32_t b0 = *(const uint32_t*)(kb);
                uint32_t b1 = *(const uint32_t*)(kb + 8);
                mma16816(c[j], qa[s][0], qa[s][1], qa[s][2], qa[s][3], b0, b1);
            }
        }

        // row max
        float tm_lo = c[0][0], tm_hi = c[0][2];
        #pragma unroll
        for (int j = 0; j < 8; j++) {
            tm_lo = fmaxf(tm_lo, fmaxf(c[j][0], c[j][1]));
            tm_hi = fmaxf(tm_hi, fmaxf(c[j][2], c[j][3]));
        }
        tm_lo = fmaxf(tm_lo, __shfl_xor_sync(0xffffffffu, tm_lo, 1));
        tm_lo = fmaxf(tm_lo, __shfl_xor_sync(0xffffffffu, tm_lo, 2));
        tm_hi = fmaxf(tm_hi, __shfl_xor_sync(0xffffffffu, tm_hi, 1));
        tm_hi = fmaxf(tm_hi, __shfl_xor_sync(0xffffffffu, tm_hi, 2));

        float mn_lo = fmaxf(m_lo, tm_lo);
        float mn_hi = fmaxf(m_hi, tm_hi);
        float al_lo = ex2f(m_lo - mn_lo);
        float al_hi = ex2f(m_hi - mn_hi);
        m_lo = mn_lo; m_hi = mn_hi;

        // P = 2^(S - m)
        #pragma unroll
        for (int j = 0; j < 8; j++) {
            c[j][0] = ex2f(c[j][0] - mn_lo);
            c[j][1] = ex2f(c[j][1] - mn_lo);
            c[j][2] = ex2f(c[j][2] - mn_hi);
            c[j][3] = ex2f(c[j][3] - mn_hi);
        }

        // rescale o and l
        #pragma unroll
        for (int j = 0; j < 8; j++) {
            o[j][0] *= al_lo; o[j][1] *= al_lo;
            o[j][2] *= al_hi; o[j][3] *= al_hi;
        }
        lacc[0] *= al_lo; lacc[1] *= al_lo;
        lacc[2] *= al_hi; lacc[3] *= al_hi;

        // O += P V ; l += P @ ones
        #pragma unroll
        for (int s = 0; s < 4; s++) {
            uint32_t a0 = packh2(c[2*s  ][0], c[2*s  ][1]);
            uint32_t a1 = packh2(c[2*s  ][2], c[2*s  ][3]);
            uint32_t a2 = packh2(c[2*s+1][0], c[2*s+1][1]);
            uint32_t a3 = packh2(c[2*s+1][2], c[2*s+1][3]);
            mma16816(lacc, a0, a1, a2, a3, ONES, ONES);
            #pragma unroll
            for (int jv = 0; jv < 8; jv++) {
                const __half* vb = vtb + (8*jv + g)*KP + 16*s + 2*t;
                uint32_t b0 = *(const uint32_t*)(vb);
                uint32_t b1 = *(const uint32_t*)(vb + 8);
                mma16816(o[jv], a0, a1, a2, a3, b0, b1);
            }
        }
    }

    // epilogue: every lane has the full row-sum in lacc (all B cols were ones)
    const float inv_lo = 1.f / lacc[0];
    const float inv_hi = 1.f / lacc[2];
    float* out_lo = out + ((size_t)n*Ss + rlo    )*Dd + h*DH;
    float* out_hi = out + ((size_t)n*Ss + rlo + 8)*Dd + h*DH;
    #pragma unroll
    for (int jv = 0; jv < 8; jv++) {
        float2 vlo = make_float2(o[jv][0]*inv_lo, o[jv][1]*inv_lo);
        float2 vhi = make_float2(o[jv][2]*inv_hi, o[jv][3]*inv_hi);
        *(float2*)(out_lo + 8*jv + 2*t) = vlo;
        *(float2*)(out_hi + 8*jv + 2*t) = vhi;
    }
}

// ---------------------------------------------------------------------------
extern "C" void kernel_launch(void* const* d_in, const int* in_sizes, int n_in,
                              void* d_out, int out_size)
{
    const float* x  = (const float*)d_in[0];
    const float* Wq = (const float*)d_in[1];
    const float* bq = (const float*)d_in[2];
    const float* Wk = (const float*)d_in[3];
    const float* bk = (const float*)d_in[4];
    const float* Wv = (const float*)d_in[5];
    const float* bv = (const float*)d_in[6];
    float* out = (float*)d_out;

    dim3 pgrid(Ss/64, Hh, Nn);   // (32, 16, 2)
    qkv_proj_kernel<<<pgrid, 128>>>(x, Wq, bq, Wk, bk, Wv, bv);

    dim3 agrid(Ss/BQ, Hh, Nn);   // (16, 16, 2)
    attn_kernel<<<agrid, 256>>>(out);
}

// round 8
// speedup vs baseline: 14.2476x; 1.0587x over previous
#include <cuda_runtime.h>
#include <cuda_fp16.h>
#include <stdint.h>
#include <math.h>

#define Nn 2
#define Ss 2048
#define Dd 1024
#define Hh 16
#define DH 64
#define BQ 128          // attn: query rows per block (8 warps x 16)
#define BK 64           // attn: keys per iteration
#define KP 72           // half smem pitch (bank-conflict-free fragments)

// Q pre-scale: (1/sqrt(DH)) * log2(e), so scores are in log2 domain for ex2.
#define QSCALE 0.18033688011112042f

// QKV scratch, fp16. v stored transposed per head.
__device__ __half g_q [(size_t)Nn*Hh*Ss*DH];
__device__ __half g_k [(size_t)Nn*Hh*Ss*DH];
__device__ __half g_vt[(size_t)Nn*Hh*DH*Ss];   // [n,h,d,s]

__device__ __forceinline__ void mma16816(float c[4],
                                         uint32_t a0, uint32_t a1, uint32_t a2, uint32_t a3,
                                         uint32_t b0, uint32_t b1)
{
    asm volatile(
        "mma.sync.aligned.m16n8k16.row.col.f32.f16.f16.f32 "
        "{%0,%1,%2,%3}, {%4,%5,%6,%7}, {%8,%9}, {%0,%1,%2,%3};\n"
        : "+f"(c[0]), "+f"(c[1]), "+f"(c[2]), "+f"(c[3])
        : "r"(a0), "r"(a1), "r"(a2), "r"(a3), "r"(b0), "r"(b1));
}

__device__ __forceinline__ uint32_t packh2(float a, float b)
{
    __half2 h = __floats2half2_rn(a, b);
    return *reinterpret_cast<uint32_t*>(&h);
}

__device__ __forceinline__ float ex2f(float x)
{
    float r;
    asm volatile("ex2.approx.f32 %0, %1;\n" : "=f"(r) : "f"(x));
    return r;
}

// two half exps in one MUFU op; input/output are packed half2
__device__ __forceinline__ uint32_t ex2h2(uint32_t x)
{
    uint32_t r;
    asm volatile("ex2.approx.f16x2 %0, %1;\n" : "=r"(r) : "r"(x));
    return r;
}

#define CP_ASYNC16(dst, src) \
    asm volatile("cp.async.cg.shared.global [%0], [%1], 16;\n" :: "r"(dst), "l"(src))
#define CP_COMMIT() asm volatile("cp.async.commit_group;\n")
#define CP_WAIT(n)  asm volatile("cp.async.wait_group %0;\n" :: "n"(n))

// ---------------------------------------------------------------------------
// Kernel 1: per-head QKV projection, fp16 tensor cores.
// ---------------------------------------------------------------------------
__global__ void __launch_bounds__(128) qkv_proj_kernel(
        const float* __restrict__ x,
        const float* __restrict__ Wq, const float* __restrict__ bq,
        const float* __restrict__ Wk, const float* __restrict__ bk,
        const float* __restrict__ Wv, const float* __restrict__ bv)
{
    __shared__ __half xs[64*KP];
    __shared__ __half ws[3][64*KP];
    __shared__ __half vs[64*KP];

    const int s0  = blockIdx.x * 64;
    const int h   = blockIdx.y;
    const int n   = blockIdx.z;
    const int tid = threadIdx.x;
    const int warp = tid >> 5;
    const int lane = tid & 31;
    const int g    = lane >> 2;
    const int t    = lane & 3;

    const float* xg = x + ((size_t)(n*Ss + s0))*Dd + h*DH;
    const float* wg[3] = { Wq + (size_t)h*DH*DH, Wk + (size_t)h*DH*DH, Wv + (size_t)h*DH*DH };
    const float* bg[3] = { bq + h*DH, bk + h*DH, bv + h*DH };

    #pragma unroll
    for (int it = 0; it < 8; it++) {
        int idx = tid + 128*it;
        int row = idx >> 4, dd = idx & 15;
        float4 v = *(const float4*)(xg + (size_t)row*Dd + 4*dd);
        *(uint32_t*)(xs + row*KP + 4*dd)     = packh2(v.x, v.y);
        *(uint32_t*)(xs + row*KP + 4*dd + 2) = packh2(v.z, v.w);
        #pragma unroll
        for (int mt = 0; mt < 3; mt++) {
            float4 w = *(const float4*)(wg[mt] + row*DH + 4*dd);
            *(uint32_t*)(ws[mt] + row*KP + 4*dd)     = packh2(w.x, w.y);
            *(uint32_t*)(ws[mt] + row*KP + 4*dd + 2) = packh2(w.z, w.w);
        }
    }
    __syncthreads();

    const int r = 16*warp + g;
    uint32_t qa[4][4];
    #pragma unroll
    for (int s = 0; s < 4; s++) {
        qa[s][0] = *(const uint32_t*)(xs + r*KP + 16*s + 2*t);
        qa[s][1] = *(const uint32_t*)(xs + (r+8)*KP + 16*s + 2*t);
        qa[s][2] = *(const uint32_t*)(xs + r*KP + 16*s + 8 + 2*t);
        qa[s][3] = *(const uint32_t*)(xs + (r+8)*KP + 16*s + 8 + 2*t);
    }

    const size_t base   = ((size_t)((n*Hh + h))*Ss + s0)*DH;
    const size_t vtbase = ((size_t)(n*Hh + h))*DH*Ss;

    #pragma unroll
    for (int mt = 0; mt < 3; mt++) {
        float c[8][4];
        #pragma unroll
        for (int j = 0; j < 8; j++) c[j][0] = c[j][1] = c[j][2] = c[j][3] = 0.f;
        #pragma unroll
        for (int j = 0; j < 8; j++) {
            #pragma unroll
            for (int s = 0; s < 4; s++) {
                const __half* wb = ws[mt] + (8*j + g)*KP + 16*s + 2*t;
                uint32_t b0 = *(const uint32_t*)(wb);
                uint32_t b1 = *(const uint32_t*)(wb + 8);
                mma16816(c[j], qa[s][0], qa[s][1], qa[s][2], qa[s][3], b0, b1);
            }
        }
        #pragma unroll
        for (int j = 0; j < 8; j++) {
            float b0 = bg[mt][8*j + 2*t];
            float b1 = bg[mt][8*j + 2*t + 1];
            float c0 = c[j][0] + b0, c1 = c[j][1] + b1;
            float c2 = c[j][2] + b0, c3 = c[j][3] + b1;
            if (mt == 0) {
                *(uint32_t*)(g_q + base + (size_t)r*DH     + 8*j + 2*t) = packh2(c0*QSCALE, c1*QSCALE);
                *(uint32_t*)(g_q + base + (size_t)(r+8)*DH + 8*j + 2*t) = packh2(c2*QSCALE, c3*QSCALE);
            } else if (mt == 1) {
                *(uint32_t*)(g_k + base + (size_t)r*DH     + 8*j + 2*t) = packh2(c0, c1);
                *(uint32_t*)(g_k + base + (size_t)(r+8)*DH + 8*j + 2*t) = packh2(c2, c3);
            } else {
                *(uint32_t*)(vs + r*KP     + 8*j + 2*t) = packh2(c0, c1);
                *(uint32_t*)(vs + (r+8)*KP + 8*j + 2*t) = packh2(c2, c3);
            }
        }
    }
    __syncthreads();

    #pragma unroll
    for (int it = 0; it < 4; it++) {
        int idx = tid + 128*it;
        int e = idx >> 3, cch = idx & 7;
        __half tmp[8];
        #pragma unroll
        for (int i = 0; i < 8; i++) tmp[i] = vs[(8*cch + i)*KP + e];
        *(float4*)(g_vt + vtbase + (size_t)e*Ss + s0 + 8*cch) = *(float4*)tmp;
    }
}

// ---------------------------------------------------------------------------
// Kernel 2: fp16 tensor-core flash attention.
// Scores in log2 domain; exp via ex2.approx.f16x2 on fp32-subtracted args.
// Row-sum l via ones-B MMA. Rescale skipped when the running max is unchanged.
// ---------------------------------------------------------------------------
__global__ void __launch_bounds__(256) attn_kernel(float* __restrict__ out)
{
    __shared__ __half Ks [2][BK*KP];   // [key][d]
    __shared__ __half Vts[2][DH*KP];   // [d][key]

    const int q0   = blockIdx.x * BQ;
    const int h    = blockIdx.y;
    const int n    = blockIdx.z;
    const int tid  = threadIdx.x;
    const int warp = tid >> 5;
    const int lane = tid & 31;
    const int g    = lane >> 2;
    const int t    = lane & 3;

    const size_t head_off = (size_t)(n*Hh + h) * Ss * DH;
    const __half* qg  = g_q  + head_off;
    const __half* kg  = g_k  + head_off;
    const __half* vtg = g_vt + head_off;

    const uint32_t sKs  = (uint32_t)__cvta_generic_to_shared(&Ks[0][0]);
    const uint32_t sVts = (uint32_t)__cvta_generic_to_shared(&Vts[0][0]);

    // Q fragments (pre-scaled by 0.125*log2e)
    const int rlo = q0 + warp*16 + g;
    const __half* q_lo = qg + (size_t)rlo*DH;
    const __half* q_hi = q_lo + 8*DH;
    uint32_t qa[4][4];
    #pragma unroll
    for (int s = 0; s < 4; s++) {
        qa[s][0] = *(const uint32_t*)(q_lo + 16*s + 2*t);
        qa[s][1] = *(const uint32_t*)(q_hi + 16*s + 2*t);
        qa[s][2] = *(const uint32_t*)(q_lo + 16*s + 8 + 2*t);
        qa[s][3] = *(const uint32_t*)(q_hi + 16*s + 8 + 2*t);
    }

    float o[8][4];
    #pragma unroll
    for (int j = 0; j < 8; j++)
        #pragma unroll
        for (int i = 0; i < 4; i++) o[j][i] = 0.f;
    float lacc[4] = {0.f, 0.f, 0.f, 0.f};
    float m_lo = -1e30f, m_hi = -1e30f;
    const uint32_t ONES = 0x3C003C00u;       // half2(1,1)

    auto load_tiles = [&](int buf, int k0) {
        #pragma unroll
        for (int it = 0; it < 2; it++) {
            int idx = tid + 256*it;
            int row = idx >> 3, c = idx & 7;
            CP_ASYNC16(sKs  + (uint32_t)((buf*BK*KP + row*KP + 8*c)*sizeof(__half)),
                       kg  + (size_t)(k0+row)*DH + 8*c);
            CP_ASYNC16(sVts + (uint32_t)((buf*DH*KP + row*KP + 8*c)*sizeof(__half)),
                       vtg + (size_t)row*Ss + k0 + 8*c);
        }
    };

    load_tiles(0, 0);
    CP_COMMIT();

    const int NT = Ss / BK;   // 32
    for (int it = 0; it < NT; it++) {
        const int cur = it & 1;
        CP_WAIT(0);
        __syncthreads();
        if (it + 1 < NT) {
            load_tiles(1 - cur, (it + 1) * BK);
            CP_COMMIT();
        }

        const __half* ksb = Ks[cur];
        const __half* vtb = Vts[cur];

        // S = Q K^T (log2 domain)
        float c[8][4];
        #pragma unroll
        for (int j = 0; j < 8; j++) {
            c[j][0] = c[j][1] = c[j][2] = c[j][3] = 0.f;
            #pragma unroll
            for (int s = 0; s < 4; s++) {
                const __half* kb = ksb + (8*j + g)*KP + 16*s + 2*t;
                uint32_t b0 = *(const uint32_t*)(kb);
                uint32_t b1 = *(const uint32_t*)(kb + 8);
                mma16816(c[j], qa[s][0], qa[s][1], qa[s][2], qa[s][3], b0, b1);
            }
        }

        // row max
        float tm_lo = c[0][0], tm_hi = c[0][2];
        #pragma unroll
        for (int j = 0; j < 8; j++) {
            tm_lo = fmaxf(tm_lo, fmaxf(c[j][0], c[j][1]));
            tm_hi = fmaxf(tm_hi, fmaxf(c[j][2], c[j][3]));
        }
        tm_lo = fmaxf(tm_lo, __shfl_xor_sync(0xffffffffu, tm_lo, 1));
        tm_lo = fmaxf(tm_lo, __shfl_xor_sync(0xffffffffu, tm_lo, 2));
        tm_hi = fmaxf(tm_hi, __shfl_xor_sync(0xffffffffu, tm_hi, 1));
        tm_hi = fmaxf(tm_hi, __shfl_xor_sync(0xffffffffu, tm_hi, 2));

        float mn_lo = fmaxf(m_lo, tm_lo);
        float mn_hi = fmaxf(m_hi, tm_hi);

        // rescale only when the running max actually moved (warp-uniform test)
        bool nochg = (mn_lo == m_lo) && (mn_hi == m_hi);
        if (!__all_sync(0xffffffffu, nochg)) {
            float al_lo = ex2f(m_lo - mn_lo);
            float al_hi = ex2f(m_hi - mn_hi);
            #pragma unroll
            for (int j = 0; j < 8; j++) {
                o[j][0] *= al_lo; o[j][1] *= al_lo;
                o[j][2] *= al_hi; o[j][3] *= al_hi;
            }
            lacc[0] *= al_lo; lacc[1] *= al_lo;
            lacc[2] *= al_hi; lacc[3] *= al_hi;
        }
        m_lo = mn_lo; m_hi = mn_hi;

        // P = 2^(S - m): subtract in fp32, exp in half2 (direct A fragments)
        uint32_t plo[8], phi[8];
        #pragma unroll
        for (int j = 0; j < 8; j++) {
            plo[j] = ex2h2(packh2(c[j][0] - mn_lo, c[j][1] - mn_lo));
            phi[j] = ex2h2(packh2(c[j][2] - mn_hi, c[j][3] - mn_hi));
        }

        // O += P V ; l += P @ ones
        #pragma unroll
        for (int s = 0; s < 4; s++) {
            uint32_t a0 = plo[2*s  ];
            uint32_t a1 = phi[2*s  ];
            uint32_t a2 = plo[2*s+1];
            uint32_t a3 = phi[2*s+1];
            mma16816(lacc, a0, a1, a2, a3, ONES, ONES);
            #pragma unroll
            for (int jv = 0; jv < 8; jv++) {
                const __half* vb = vtb + (8*jv + g)*KP + 16*s + 2*t;
                uint32_t b0 = *(const uint32_t*)(vb);
                uint32_t b1 = *(const uint32_t*)(vb + 8);
                mma16816(o[jv], a0, a1, a2, a3, b0, b1);
            }
        }
    }

    // epilogue
    const float inv_lo = 1.f / lacc[0];
    const float inv_hi = 1.f / lacc[2];
    float* out_lo = out + ((size_t)n*Ss + rlo    )*Dd + h*DH;
    float* out_hi = out + ((size_t)n*Ss + rlo + 8)*Dd + h*DH;
    #pragma unroll
    for (int jv = 0; jv < 8; jv++) {
        float2 vlo = make_float2(o[jv][0]*inv_lo, o[jv][1]*inv_lo);
        float2 vhi = make_float2(o[jv][2]*inv_hi, o[jv][3]*inv_hi);
        *(float2*)(out_lo + 8*jv + 2*t) = vlo;
        *(float2*)(out_hi + 8*jv + 2*t) = vhi;
    }
}

// ---------------------------------------------------------------------------
extern "C" void kernel_launch(void* const* d_in, const int* in_sizes, int n_in,
                              void* d_out, int out_size)
{
    const float* x  = (const float*)d_in[0];
    const float* Wq = (const float*)d_in[1];
    const float* bq = (const float*)d_in[2];
    const float* Wk = (const float*)d_in[3];
    const float* bk = (const float*)d_in[4];
    const float* Wv = (const float*)d_in[5];
    const float* bv = (const float*)d_in[6];
    float* out = (float*)d_out;

    dim3 pgrid(Ss/64, Hh, Nn);   // (32, 16, 2)
    qkv_proj_kernel<<<pgrid, 128>>>(x, Wq, bq, Wk, bk, Wv, bv);

    dim3 agrid(Ss/BQ, Hh, Nn);   // (16, 16, 2)
    attn_kernel<<<agrid, 256>>>(out);
}

// round 9
// speedup vs baseline: 14.5189x; 1.0190x over previous
#include <cuda_runtime.h>
#include <cuda_fp16.h>
#include <stdint.h>
#include <math.h>

#define Nn 2
#define Ss 2048
#define Dd 1024
#define Hh 16
#define DH 64
#define BQ 128          // attn: query rows per block (4 warps x 32)
#define BK 64           // attn: keys per iteration
#define KP 72           // half smem pitch (bank-conflict-free fragments)

// Q pre-scale: (1/sqrt(DH)) * log2(e), so scores are in log2 domain for ex2.
#define QSCALE 0.18033688011112042f

// QKV scratch, fp16. v stored transposed per head.
__device__ __half g_q [(size_t)Nn*Hh*Ss*DH];
__device__ __half g_k [(size_t)Nn*Hh*Ss*DH];
__device__ __half g_vt[(size_t)Nn*Hh*DH*Ss];   // [n,h,d,s]

__device__ __forceinline__ void mma16816(float c[4],
                                         uint32_t a0, uint32_t a1, uint32_t a2, uint32_t a3,
                                         uint32_t b0, uint32_t b1)
{
    asm volatile(
        "mma.sync.aligned.m16n8k16.row.col.f32.f16.f16.f32 "
        "{%0,%1,%2,%3}, {%4,%5,%6,%7}, {%8,%9}, {%0,%1,%2,%3};\n"
        : "+f"(c[0]), "+f"(c[1]), "+f"(c[2]), "+f"(c[3])
        : "r"(a0), "r"(a1), "r"(a2), "r"(a3), "r"(b0), "r"(b1));
}

__device__ __forceinline__ uint32_t packh2(float a, float b)
{
    __half2 h = __floats2half2_rn(a, b);
    return *reinterpret_cast<uint32_t*>(&h);
}

__device__ __forceinline__ float ex2f(float x)
{
    float r;
    asm volatile("ex2.approx.f32 %0, %1;\n" : "=f"(r) : "f"(x));
    return r;
}

__device__ __forceinline__ uint32_t ex2h2(uint32_t x)
{
    uint32_t r;
    asm volatile("ex2.approx.f16x2 %0, %1;\n" : "=r"(r) : "r"(x));
    return r;
}

#define CP_ASYNC16(dst, src) \
    asm volatile("cp.async.cg.shared.global [%0], [%1], 16;\n" :: "r"(dst), "l"(src))
#define CP_COMMIT() asm volatile("cp.async.commit_group;\n")
#define CP_WAIT(n)  asm volatile("cp.async.wait_group %0;\n" :: "n"(n))

// ---------------------------------------------------------------------------
// Kernel 1: per-head QKV projection, fp16 tensor cores (unchanged).
// ---------------------------------------------------------------------------
__global__ void __launch_bounds__(128) qkv_proj_kernel(
        const float* __restrict__ x,
        const float* __restrict__ Wq, const float* __restrict__ bq,
        const float* __restrict__ Wk, const float* __restrict__ bk,
        const float* __restrict__ Wv, const float* __restrict__ bv)
{
    __shared__ __half xs[64*KP];
    __shared__ __half ws[3][64*KP];
    __shared__ __half vs[64*KP];

    const int s0  = blockIdx.x * 64;
    const int h   = blockIdx.y;
    const int n   = blockIdx.z;
    const int tid = threadIdx.x;
    const int warp = tid >> 5;
    const int lane = tid & 31;
    const int g    = lane >> 2;
    const int t    = lane & 3;

    const float* xg = x + ((size_t)(n*Ss + s0))*Dd + h*DH;
    const float* wg[3] = { Wq + (size_t)h*DH*DH, Wk + (size_t)h*DH*DH, Wv + (size_t)h*DH*DH };
    const float* bg[3] = { bq + h*DH, bk + h*DH, bv + h*DH };

    #pragma unroll
    for (int it = 0; it < 8; it++) {
        int idx = tid + 128*it;
        int row = idx >> 4, dd = idx & 15;
        float4 v = *(const float4*)(xg + (size_t)row*Dd + 4*dd);
        *(uint32_t*)(xs + row*KP + 4*dd)     = packh2(v.x, v.y);
        *(uint32_t*)(xs + row*KP + 4*dd + 2) = packh2(v.z, v.w);
        #pragma unroll
        for (int mt = 0; mt < 3; mt++) {
            float4 w = *(const float4*)(wg[mt] + row*DH + 4*dd);
            *(uint32_t*)(ws[mt] + row*KP + 4*dd)     = packh2(w.x, w.y);
            *(uint32_t*)(ws[mt] + row*KP + 4*dd + 2) = packh2(w.z, w.w);
        }
    }
    __syncthreads();

    const int r = 16*warp + g;
    uint32_t qa[4][4];
    #pragma unroll
    for (int s = 0; s < 4; s++) {
        qa[s][0] = *(const uint32_t*)(xs + r*KP + 16*s + 2*t);
        qa[s][1] = *(const uint32_t*)(xs + (r+8)*KP + 16*s + 2*t);
        qa[s][2] = *(const uint32_t*)(xs + r*KP + 16*s + 8 + 2*t);
        qa[s][3] = *(const uint32_t*)(xs + (r+8)*KP + 16*s + 8 + 2*t);
    }

    const size_t base   = ((size_t)((n*Hh + h))*Ss + s0)*DH;
    const size_t vtbase = ((size_t)(n*Hh + h))*DH*Ss;

    #pragma unroll
    for (int mt = 0; mt < 3; mt++) {
        float c[8][4];
        #pragma unroll
        for (int j = 0; j < 8; j++) c[j][0] = c[j][1] = c[j][2] = c[j][3] = 0.f;
        #pragma unroll
        for (int j = 0; j < 8; j++) {
            #pragma unroll
            for (int s = 0; s < 4; s++) {
                const __half* wb = ws[mt] + (8*j + g)*KP + 16*s + 2*t;
                uint32_t b0 = *(const uint32_t*)(wb);
                uint32_t b1 = *(const uint32_t*)(wb + 8);
                mma16816(c[j], qa[s][0], qa[s][1], qa[s][2], qa[s][3], b0, b1);
            }
        }
        #pragma unroll
        for (int j = 0; j < 8; j++) {
            float b0 = bg[mt][8*j + 2*t];
            float b1 = bg[mt][8*j + 2*t + 1];
            float c0 = c[j][0] + b0, c1 = c[j][1] + b1;
            float c2 = c[j][2] + b0, c3 = c[j][3] + b1;
            if (mt == 0) {
                *(uint32_t*)(g_q + base + (size_t)r*DH     + 8*j + 2*t) = packh2(c0*QSCALE, c1*QSCALE);
                *(uint32_t*)(g_q + base + (size_t)(r+8)*DH + 8*j + 2*t) = packh2(c2*QSCALE, c3*QSCALE);
            } else if (mt == 1) {
                *(uint32_t*)(g_k + base + (size_t)r*DH     + 8*j + 2*t) = packh2(c0, c1);
                *(uint32_t*)(g_k + base + (size_t)(r+8)*DH + 8*j + 2*t) = packh2(c2, c3);
            } else {
                *(uint32_t*)(vs + r*KP     + 8*j + 2*t) = packh2(c0, c1);
                *(uint32_t*)(vs + (r+8)*KP + 8*j + 2*t) = packh2(c2, c3);
            }
        }
    }
    __syncthreads();

    #pragma unroll
    for (int it = 0; it < 4; it++) {
        int idx = tid + 128*it;
        int e = idx >> 3, cch = idx & 7;
        __half tmp[8];
        #pragma unroll
        for (int i = 0; i < 8; i++) tmp[i] = vs[(8*cch + i)*KP + e];
        *(float4*)(g_vt + vtbase + (size_t)e*Ss + s0 + 8*cch) = *(float4*)tmp;
    }
}

// ---------------------------------------------------------------------------
// Kernel 2: fp16 tensor-core flash attention; 4 warps, M=32 rows per warp.
// Each B fragment load feeds TWO MMAs (row strips 0/1) -> half the smem
// fragment traffic per unit of tensor work.
// ---------------------------------------------------------------------------
__global__ void __launch_bounds__(128) attn_kernel(float* __restrict__ out)
{
    __shared__ __half Ks [2][BK*KP];   // [key][d]
    __shared__ __half Vts[2][DH*KP];   // [d][key]

    const int q0   = blockIdx.x * BQ;
    const int h    = blockIdx.y;
    const int n    = blockIdx.z;
    const int tid  = threadIdx.x;
    const int warp = tid >> 5;         // 0..3
    const int lane = tid & 31;
    const int g    = lane >> 2;
    const int t    = lane & 3;

    const size_t head_off = (size_t)(n*Hh + h) * Ss * DH;
    const __half* qg  = g_q  + head_off;
    const __half* kg  = g_k  + head_off;
    const __half* vtg = g_vt + head_off;

    const uint32_t sKs  = (uint32_t)__cvta_generic_to_shared(&Ks[0][0]);
    const uint32_t sVts = (uint32_t)__cvta_generic_to_shared(&Vts[0][0]);

    // Q fragments for two 16-row strips (rows warp*32 + 16*st + {g, g+8})
    const int rbase = q0 + warp*32;
    uint32_t qa[2][4][4];
    #pragma unroll
    for (int st = 0; st < 2; st++) {
        const __half* q_lo = qg + (size_t)(rbase + 16*st + g)*DH;
        const __half* q_hi = q_lo + 8*DH;
        #pragma unroll
        for (int s = 0; s < 4; s++) {
            qa[st][s][0] = *(const uint32_t*)(q_lo + 16*s + 2*t);
            qa[st][s][1] = *(const uint32_t*)(q_hi + 16*s + 2*t);
            qa[st][s][2] = *(const uint32_t*)(q_lo + 16*s + 8 + 2*t);
            qa[st][s][3] = *(const uint32_t*)(q_hi + 16*s + 8 + 2*t);
        }
    }

    float o[2][8][4];
    #pragma unroll
    for (int st = 0; st < 2; st++)
        #pragma unroll
        for (int j = 0; j < 8; j++)
            #pragma unroll
            for (int i = 0; i < 4; i++) o[st][j][i] = 0.f;
    float lacc[2][4] = {{0.f,0.f,0.f,0.f},{0.f,0.f,0.f,0.f}};
    float m[2][2] = {{-1e30f,-1e30f},{-1e30f,-1e30f}};   // [st][lo/hi]
    const uint32_t ONES = 0x3C003C00u;

    auto load_tiles = [&](int buf, int k0) {
        #pragma unroll
        for (int it = 0; it < 4; it++) {
            int idx = tid + 128*it;          // 0..511
            int row = idx >> 3, c = idx & 7;
            CP_ASYNC16(sKs  + (uint32_t)((buf*BK*KP + row*KP + 8*c)*sizeof(__half)),
                       kg  + (size_t)(k0+row)*DH + 8*c);
            CP_ASYNC16(sVts + (uint32_t)((buf*DH*KP + row*KP + 8*c)*sizeof(__half)),
                       vtg + (size_t)row*Ss + k0 + 8*c);
        }
    };

    load_tiles(0, 0);
    CP_COMMIT();

    const int NT = Ss / BK;   // 32
    for (int it = 0; it < NT; it++) {
        const int cur = it & 1;
        CP_WAIT(0);
        __syncthreads();
        if (it + 1 < NT) {
            load_tiles(1 - cur, (it + 1) * BK);
            CP_COMMIT();
        }

        const __half* ksb = Ks[cur];
        const __half* vtb = Vts[cur];

        // S = Q K^T for both strips; each (b0,b1) feeds two MMAs
        float c0[8][4], c1[8][4];
        #pragma unroll
        for (int j = 0; j < 8; j++) {
            c0[j][0]=c0[j][1]=c0[j][2]=c0[j][3]=0.f;
            c1[j][0]=c1[j][1]=c1[j][2]=c1[j][3]=0.f;
            #pragma unroll
            for (int s = 0; s < 4; s++) {
                const __half* kb = ksb + (8*j + g)*KP + 16*s + 2*t;
                uint32_t b0 = *(const uint32_t*)(kb);
                uint32_t b1 = *(const uint32_t*)(kb + 8);
                mma16816(c0[j], qa[0][s][0], qa[0][s][1], qa[0][s][2], qa[0][s][3], b0, b1);
                mma16816(c1[j], qa[1][s][0], qa[1][s][1], qa[1][s][2], qa[1][s][3], b0, b1);
            }
        }

        // row max per strip
        float tm[2][2];
        {
            float a = c0[0][0], b = c0[0][2], e = c1[0][0], f = c1[0][2];
            #pragma unroll
            for (int j = 0; j < 8; j++) {
                a = fmaxf(a, fmaxf(c0[j][0], c0[j][1]));
                b = fmaxf(b, fmaxf(c0[j][2], c0[j][3]));
                e = fmaxf(e, fmaxf(c1[j][0], c1[j][1]));
                f = fmaxf(f, fmaxf(c1[j][2], c1[j][3]));
            }
            tm[0][0]=a; tm[0][1]=b; tm[1][0]=e; tm[1][1]=f;
        }
        #pragma unroll
        for (int st = 0; st < 2; st++) {
            #pragma unroll
            for (int k = 0; k < 2; k++) {
                tm[st][k] = fmaxf(tm[st][k], __shfl_xor_sync(0xffffffffu, tm[st][k], 1));
                tm[st][k] = fmaxf(tm[st][k], __shfl_xor_sync(0xffffffffu, tm[st][k], 2));
            }
        }

        float mn[2][2];
        #pragma unroll
        for (int st = 0; st < 2; st++) {
            mn[st][0] = fmaxf(m[st][0], tm[st][0]);
            mn[st][1] = fmaxf(m[st][1], tm[st][1]);
        }

        bool nochg = (mn[0][0]==m[0][0]) && (mn[0][1]==m[0][1])
                  && (mn[1][0]==m[1][0]) && (mn[1][1]==m[1][1]);
        if (!__all_sync(0xffffffffu, nochg)) {
            #pragma unroll
            for (int st = 0; st < 2; st++) {
                float al_lo = ex2f(m[st][0] - mn[st][0]);
                float al_hi = ex2f(m[st][1] - mn[st][1]);
                #pragma unroll
                for (int j = 0; j < 8; j++) {
                    o[st][j][0] *= al_lo; o[st][j][1] *= al_lo;
                    o[st][j][2] *= al_hi; o[st][j][3] *= al_hi;
                }
                lacc[st][0] *= al_lo; lacc[st][1] *= al_lo;
                lacc[st][2] *= al_hi; lacc[st][3] *= al_hi;
            }
        }
        #pragma unroll
        for (int st = 0; st < 2; st++) { m[st][0] = mn[st][0]; m[st][1] = mn[st][1]; }

        // P = 2^(S-m) as packed half2 A fragments
        uint32_t p0lo[8], p0hi[8], p1lo[8], p1hi[8];
        #pragma unroll
        for (int j = 0; j < 8; j++) {
            p0lo[j] = ex2h2(packh2(c0[j][0] - mn[0][0], c0[j][1] - mn[0][0]));
            p0hi[j] = ex2h2(packh2(c0[j][2] - mn[0][1], c0[j][3] - mn[0][1]));
            p1lo[j] = ex2h2(packh2(c1[j][0] - mn[1][0], c1[j][1] - mn[1][0]));
            p1hi[j] = ex2h2(packh2(c1[j][2] - mn[1][1], c1[j][3] - mn[1][1]));
        }

        // O += P V ; l += P @ ones. Each (b0,b1) feeds both strips.
        #pragma unroll
        for (int s = 0; s < 4; s++) {
            uint32_t a00 = p0lo[2*s], a01 = p0hi[2*s], a02 = p0lo[2*s+1], a03 = p0hi[2*s+1];
            uint32_t a10 = p1lo[2*s], a11 = p1hi[2*s], a12 = p1lo[2*s+1], a13 = p1hi[2*s+1];
            mma16816(lacc[0], a00, a01, a02, a03, ONES, ONES);
            mma16816(lacc[1], a10, a11, a12, a13, ONES, ONES);
            #pragma unroll
            for (int jv = 0; jv < 8; jv++) {
                const __half* vb = vtb + (8*jv + g)*KP + 16*s + 2*t;
                uint32_t b0 = *(const uint32_t*)(vb);
                uint32_t b1 = *(const uint32_t*)(vb + 8);
                mma16816(o[0][jv], a00, a01, a02, a03, b0, b1);
                mma16816(o[1][jv], a10, a11, a12, a13, b0, b1);
            }
        }
    }

    // epilogue
    #pragma unroll
    for (int st = 0; st < 2; st++) {
        const float inv_lo = 1.f / lacc[st][0];
        const float inv_hi = 1.f / lacc[st][2];
        float* out_lo = out + ((size_t)n*Ss + rbase + 16*st + g    )*Dd + h*DH;
        float* out_hi = out + ((size_t)n*Ss + rbase + 16*st + g + 8)*Dd + h*DH;
        #pragma unroll
        for (int jv = 0; jv < 8; jv++) {
            float2 vlo = make_float2(o[st][jv][0]*inv_lo, o[st][jv][1]*inv_lo);
            float2 vhi = make_float2(o[st][jv][2]*inv_hi, o[st][jv][3]*inv_hi);
            *(float2*)(out_lo + 8*jv + 2*t) = vlo;
            *(float2*)(out_hi + 8*jv + 2*t) = vhi;
        }
    }
}

// ---------------------------------------------------------------------------
extern "C" void kernel_launch(void* const* d_in, const int* in_sizes, int n_in,
                              void* d_out, int out_size)
{
    const float* x  = (const float*)d_in[0];
    const float* Wq = (const float*)d_in[1];
    const float* bq = (const float*)d_in[2];
    const float* Wk = (const float*)d_in[3];
    const float* bk = (const float*)d_in[4];
    const float* Wv = (const float*)d_in[5];
    const float* bv = (const float*)d_in[6];
    float* out = (float*)d_out;

    dim3 pgrid(Ss/64, Hh, Nn);   // (32, 16, 2)
    qkv_proj_kernel<<<pgrid, 128>>>(x, Wq, bq, Wk, bk, Wv, bv);

    dim3 agrid(Ss/BQ, Hh, Nn);   // (16, 16, 2)
    attn_kernel<<<agrid, 128>>>(out);
}

// round 10
// speedup vs baseline: 15.1152x; 1.0411x over previous
#include <cuda_runtime.h>
#include <cuda_fp16.h>
#include <stdint.h>
#include <math.h>

#define Nn 2
#define Ss 2048
#define Dd 1024
#define Hh 16
#define DH 64
#define BQ 128          // attn: query rows per block (4 warps x 32)
#define BK 64           // attn: keys per iteration
#define KP 72           // half smem pitch (bank-conflict-free fragments + ldmatrix)

// Q pre-scale: (1/sqrt(DH)) * log2(e), so scores are in log2 domain for ex2.
#define QSCALE 0.18033688011112042f

// QKV scratch, fp16. v stored transposed per head.
__device__ __half g_q [(size_t)Nn*Hh*Ss*DH];
__device__ __half g_k [(size_t)Nn*Hh*Ss*DH];
__device__ __half g_vt[(size_t)Nn*Hh*DH*Ss];   // [n,h,d,s]

__device__ __forceinline__ void mma16816(float c[4],
                                         uint32_t a0, uint32_t a1, uint32_t a2, uint32_t a3,
                                         uint32_t b0, uint32_t b1)
{
    asm volatile(
        "mma.sync.aligned.m16n8k16.row.col.f32.f16.f16.f32 "
        "{%0,%1,%2,%3}, {%4,%5,%6,%7}, {%8,%9}, {%0,%1,%2,%3};\n"
        : "+f"(c[0]), "+f"(c[1]), "+f"(c[2]), "+f"(c[3])
        : "r"(a0), "r"(a1), "r"(a2), "r"(a3), "r"(b0), "r"(b1));
}

__device__ __forceinline__ void ldsm4(uint32_t& r0, uint32_t& r1,
                                      uint32_t& r2, uint32_t& r3, uint32_t addr)
{
    asm volatile("ldmatrix.sync.aligned.m8n8.x4.shared.b16 {%0,%1,%2,%3}, [%4];\n"
                 : "=r"(r0), "=r"(r1), "=r"(r2), "=r"(r3) : "r"(addr));
}

__device__ __forceinline__ uint32_t packh2(float a, float b)
{
    __half2 h = __floats2half2_rn(a, b);
    return *reinterpret_cast<uint32_t*>(&h);
}

__device__ __forceinline__ float ex2f(float x)
{
    float r;
    asm volatile("ex2.approx.f32 %0, %1;\n" : "=f"(r) : "f"(x));
    return r;
}

__device__ __forceinline__ uint32_t ex2h2(uint32_t x)
{
    uint32_t r;
    asm volatile("ex2.approx.f16x2 %0, %1;\n" : "=r"(r) : "r"(x));
    return r;
}

#define CP_ASYNC16(dst, src) \
    asm volatile("cp.async.cg.shared.global [%0], [%1], 16;\n" :: "r"(dst), "l"(src))
#define CP_COMMIT() asm volatile("cp.async.commit_group;\n")
#define CP_WAIT(n)  asm volatile("cp.async.wait_group %0;\n" :: "n"(n))

// ---------------------------------------------------------------------------
// Kernel 1: per-head QKV projection, fp16 tensor cores (unchanged).
// ---------------------------------------------------------------------------
__global__ void __launch_bounds__(128) qkv_proj_kernel(
        const float* __restrict__ x,
        const float* __restrict__ Wq, const float* __restrict__ bq,
        const float* __restrict__ Wk, const float* __restrict__ bk,
        const float* __restrict__ Wv, const float* __restrict__ bv)
{
    __shared__ __half xs[64*KP];
    __shared__ __half ws[3][64*KP];
    __shared__ __half vs[64*KP];

    const int s0  = blockIdx.x * 64;
    const int h   = blockIdx.y;
    const int n   = blockIdx.z;
    const int tid = threadIdx.x;
    const int warp = tid >> 5;
    const int lane = tid & 31;
    const int g    = lane >> 2;
    const int t    = lane & 3;

    const float* xg = x + ((size_t)(n*Ss + s0))*Dd + h*DH;
    const float* wg[3] = { Wq + (size_t)h*DH*DH, Wk + (size_t)h*DH*DH, Wv + (size_t)h*DH*DH };
    const float* bg[3] = { bq + h*DH, bk + h*DH, bv + h*DH };

    #pragma unroll
    for (int it = 0; it < 8; it++) {
        int idx = tid + 128*it;
        int row = idx >> 4, dd = idx & 15;
        float4 v = *(const float4*)(xg + (size_t)row*Dd + 4*dd);
        *(uint32_t*)(xs + row*KP + 4*dd)     = packh2(v.x, v.y);
        *(uint32_t*)(xs + row*KP + 4*dd + 2) = packh2(v.z, v.w);
        #pragma unroll
        for (int mt = 0; mt < 3; mt++) {
            float4 w = *(const float4*)(wg[mt] + row*DH + 4*dd);
            *(uint32_t*)(ws[mt] + row*KP + 4*dd)     = packh2(w.x, w.y);
            *(uint32_t*)(ws[mt] + row*KP + 4*dd + 2) = packh2(w.z, w.w);
        }
    }
    __syncthreads();

    const int r = 16*warp + g;
    uint32_t qa[4][4];
    #pragma unroll
    for (int s = 0; s < 4; s++) {
        qa[s][0] = *(const uint32_t*)(xs + r*KP + 16*s + 2*t);
        qa[s][1] = *(const uint32_t*)(xs + (r+8)*KP + 16*s + 2*t);
        qa[s][2] = *(const uint32_t*)(xs + r*KP + 16*s + 8 + 2*t);
        qa[s][3] = *(const uint32_t*)(xs + (r+8)*KP + 16*s + 8 + 2*t);
    }

    const size_t base   = ((size_t)((n*Hh + h))*Ss + s0)*DH;
    const size_t vtbase = ((size_t)(n*Hh + h))*DH*Ss;

    #pragma unroll
    for (int mt = 0; mt < 3; mt++) {
        float c[8][4];
        #pragma unroll
        for (int j = 0; j < 8; j++) c[j][0] = c[j][1] = c[j][2] = c[j][3] = 0.f;
        #pragma unroll
        for (int j = 0; j < 8; j++) {
            #pragma unroll
            for (int s = 0; s < 4; s++) {
                const __half* wb = ws[mt] + (8*j + g)*KP + 16*s + 2*t;
                uint32_t b0 = *(const uint32_t*)(wb);
                uint32_t b1 = *(const uint32_t*)(wb + 8);
                mma16816(c[j], qa[s][0], qa[s][1], qa[s][2], qa[s][3], b0, b1);
            }
        }
        #pragma unroll
        for (int j = 0; j < 8; j++) {
            float b0 = bg[mt][8*j + 2*t];
            float b1 = bg[mt][8*j + 2*t + 1];
            float c0 = c[j][0] + b0, c1 = c[j][1] + b1;
            float c2 = c[j][2] + b0, c3 = c[j][3] + b1;
            if (mt == 0) {
                *(uint32_t*)(g_q + base + (size_t)r*DH     + 8*j + 2*t) = packh2(c0*QSCALE, c1*QSCALE);
                *(uint32_t*)(g_q + base + (size_t)(r+8)*DH + 8*j + 2*t) = packh2(c2*QSCALE, c3*QSCALE);
            } else if (mt == 1) {
                *(uint32_t*)(g_k + base + (size_t)r*DH     + 8*j + 2*t) = packh2(c0, c1);
                *(uint32_t*)(g_k + base + (size_t)(r+8)*DH + 8*j + 2*t) = packh2(c2, c3);
            } else {
                *(uint32_t*)(vs + r*KP     + 8*j + 2*t) = packh2(c0, c1);
                *(uint32_t*)(vs + (r+8)*KP + 8*j + 2*t) = packh2(c2, c3);
            }
        }
    }
    __syncthreads();

    #pragma unroll
    for (int it = 0; it < 4; it++) {
        int idx = tid + 128*it;
        int e = idx >> 3, cch = idx & 7;
        __half tmp[8];
        #pragma unroll
        for (int i = 0; i < 8; i++) tmp[i] = vs[(8*cch + i)*KP + e];
        *(float4*)(g_vt + vtbase + (size_t)e*Ss + s0 + 8*cch) = *(float4*)tmp;
    }
}

// ---------------------------------------------------------------------------
// Kernel 2: fp16 tensor-core flash attention; 4 warps, M=32 rows per warp.
// B fragments loaded via ldmatrix.x4 (2 instr per 8x64 row-strip instead of
// 8 LDS.32), each fragment set feeds both row strips.
// ---------------------------------------------------------------------------
__global__ void __launch_bounds__(128) attn_kernel(float* __restrict__ out)
{
    __shared__ __half Ks [2][BK*KP];   // [key][d]
    __shared__ __half Vts[2][DH*KP];   // [d][key]

    const int q0   = blockIdx.x * BQ;
    const int h    = blockIdx.y;
    const int n    = blockIdx.z;
    const int tid  = threadIdx.x;
    const int warp = tid >> 5;         // 0..3
    const int lane = tid & 31;
    const int g    = lane >> 2;
    const int t    = lane & 3;

    const size_t head_off = (size_t)(n*Hh + h) * Ss * DH;
    const __half* qg  = g_q  + head_off;
    const __half* kg  = g_k  + head_off;
    const __half* vtg = g_vt + head_off;

    const uint32_t sKs  = (uint32_t)__cvta_generic_to_shared(&Ks[0][0]);
    const uint32_t sVts = (uint32_t)__cvta_generic_to_shared(&Vts[0][0]);
    const uint32_t BUFK = (uint32_t)(BK*KP*sizeof(__half));   // 9216
    const uint32_t BUFV = (uint32_t)(DH*KP*sizeof(__half));   // 9216

    // per-lane ldmatrix base: row = lane&7, tile col = lane>>3 (16B each)
    const uint32_t lm_off = (uint32_t)((lane & 7) * KP * sizeof(__half) + (lane >> 3) * 16);

    // Q fragments for two 16-row strips (rows warp*32 + 16*st + {g, g+8})
    const int rbase = q0 + warp*32;
    uint32_t qa[2][4][4];
    #pragma unroll
    for (int st = 0; st < 2; st++) {
        const __half* q_lo = qg + (size_t)(rbase + 16*st + g)*DH;
        const __half* q_hi = q_lo + 8*DH;
        #pragma unroll
        for (int s = 0; s < 4; s++) {
            qa[st][s][0] = *(const uint32_t*)(q_lo + 16*s + 2*t);
            qa[st][s][1] = *(const uint32_t*)(q_hi + 16*s + 2*t);
            qa[st][s][2] = *(const uint32_t*)(q_lo + 16*s + 8 + 2*t);
            qa[st][s][3] = *(const uint32_t*)(q_hi + 16*s + 8 + 2*t);
        }
    }

    float o[2][8][4];
    #pragma unroll
    for (int st = 0; st < 2; st++)
        #pragma unroll
        for (int j = 0; j < 8; j++)
            #pragma unroll
            for (int i = 0; i < 4; i++) o[st][j][i] = 0.f;
    float lacc[2][4] = {{0.f,0.f,0.f,0.f},{0.f,0.f,0.f,0.f}};
    float m[2][2] = {{-1e30f,-1e30f},{-1e30f,-1e30f}};   // [st][lo/hi]
    const uint32_t ONES = 0x3C003C00u;

    auto load_tiles = [&](int buf, int k0) {
        #pragma unroll
        for (int it = 0; it < 4; it++) {
            int idx = tid + 128*it;          // 0..511
            int row = idx >> 3, c = idx & 7;
            CP_ASYNC16(sKs  + (uint32_t)(buf*BUFK + (row*KP + 8*c)*sizeof(__half)),
                       kg  + (size_t)(k0+row)*DH + 8*c);
            CP_ASYNC16(sVts + (uint32_t)(buf*BUFV + (row*KP + 8*c)*sizeof(__half)),
                       vtg + (size_t)row*Ss + k0 + 8*c);
        }
    };

    load_tiles(0, 0);
    CP_COMMIT();

    const int NT = Ss / BK;   // 32
    for (int it = 0; it < NT; it++) {
        const int cur = it & 1;
        CP_WAIT(0);
        __syncthreads();
        if (it + 1 < NT) {
            load_tiles(1 - cur, (it + 1) * BK);
            CP_COMMIT();
        }

        const uint32_t kbase = sKs  + cur*BUFK + lm_off;
        const uint32_t vbase = sVts + cur*BUFV + lm_off;

        // S = Q K^T for both strips; fragments via ldmatrix, reused by both strips
        float c0[8][4], c1[8][4];
        #pragma unroll
        for (int j = 0; j < 8; j++) {
            c0[j][0]=c0[j][1]=c0[j][2]=c0[j][3]=0.f;
            c1[j][0]=c1[j][1]=c1[j][2]=c1[j][3]=0.f;
            uint32_t b[8];
            uint32_t a = kbase + (uint32_t)(j*8*KP*sizeof(__half));
            ldsm4(b[0], b[1], b[2], b[3], a);
            ldsm4(b[4], b[5], b[6], b[7], a + 64);
            #pragma unroll
            for (int s = 0; s < 4; s++) {
                mma16816(c0[j], qa[0][s][0], qa[0][s][1], qa[0][s][2], qa[0][s][3], b[2*s], b[2*s+1]);
                mma16816(c1[j], qa[1][s][0], qa[1][s][1], qa[1][s][2], qa[1][s][3], b[2*s], b[2*s+1]);
            }
        }

        // row max per strip
        float tm[2][2];
        {
            float a = c0[0][0], b = c0[0][2], e = c1[0][0], f = c1[0][2];
            #pragma unroll
            for (int j = 0; j < 8; j++) {
                a = fmaxf(a, fmaxf(c0[j][0], c0[j][1]));
                b = fmaxf(b, fmaxf(c0[j][2], c0[j][3]));
                e = fmaxf(e, fmaxf(c1[j][0], c1[j][1]));
                f = fmaxf(f, fmaxf(c1[j][2], c1[j][3]));
            }
            tm[0][0]=a; tm[0][1]=b; tm[1][0]=e; tm[1][1]=f;
        }
        #pragma unroll
        for (int st = 0; st < 2; st++) {
            #pragma unroll
            for (int k = 0; k < 2; k++) {
                tm[st][k] = fmaxf(tm[st][k], __shfl_xor_sync(0xffffffffu, tm[st][k], 1));
                tm[st][k] = fmaxf(tm[st][k], __shfl_xor_sync(0xffffffffu, tm[st][k], 2));
            }
        }

        float mn[2][2];
        #pragma unroll
        for (int st = 0; st < 2; st++) {
            mn[st][0] = fmaxf(m[st][0], tm[st][0]);
            mn[st][1] = fmaxf(m[st][1], tm[st][1]);
        }

        bool nochg = (mn[0][0]==m[0][0]) && (mn[0][1]==m[0][1])
                  && (mn[1][0]==m[1][0]) && (mn[1][1]==m[1][1]);
        if (!__all_sync(0xffffffffu, nochg)) {
            #pragma unroll
            for (int st = 0; st < 2; st++) {
                float al_lo = ex2f(m[st][0] - mn[st][0]);
                float al_hi = ex2f(m[st][1] - mn[st][1]);
                #pragma unroll
                for (int j = 0; j < 8; j++) {
                    o[st][j][0] *= al_lo; o[st][j][1] *= al_lo;
                    o[st][j][2] *= al_hi; o[st][j][3] *= al_hi;
                }
                lacc[st][0] *= al_lo; lacc[st][1] *= al_lo;
                lacc[st][2] *= al_hi; lacc[st][3] *= al_hi;
            }
        }
        #pragma unroll
        for (int st = 0; st < 2; st++) { m[st][0] = mn[st][0]; m[st][1] = mn[st][1]; }

        // P = 2^(S-m) as packed half2 A fragments
        uint32_t p0lo[8], p0hi[8], p1lo[8], p1hi[8];
        #pragma unroll
        for (int j = 0; j < 8; j++) {
            p0lo[j] = ex2h2(packh2(c0[j][0] - mn[0][0], c0[j][1] - mn[0][0]));
            p0hi[j] = ex2h2(packh2(c0[j][2] - mn[0][1], c0[j][3] - mn[0][1]));
            p1lo[j] = ex2h2(packh2(c1[j][0] - mn[1][0], c1[j][1] - mn[1][0]));
            p1hi[j] = ex2h2(packh2(c1[j][2] - mn[1][1], c1[j][3] - mn[1][1]));
        }

        // O += P V ; l += P @ ones. V fragments via ldmatrix, feed both strips.
        #pragma unroll
        for (int jv = 0; jv < 8; jv++) {
            uint32_t b[8];
            uint32_t a = vbase + (uint32_t)(jv*8*KP*sizeof(__half));
            ldsm4(b[0], b[1], b[2], b[3], a);
            ldsm4(b[4], b[5], b[6], b[7], a + 64);
            #pragma unroll
            for (int s = 0; s < 4; s++) {
                mma16816(o[0][jv], p0lo[2*s], p0hi[2*s], p0lo[2*s+1], p0hi[2*s+1], b[2*s], b[2*s+1]);
                mma16816(o[1][jv], p1lo[2*s], p1hi[2*s], p1lo[2*s+1], p1hi[2*s+1], b[2*s], b[2*s+1]);
            }
        }
        #pragma unroll
        for (int s = 0; s < 4; s++) {
            mma16816(lacc[0], p0lo[2*s], p0hi[2*s], p0lo[2*s+1], p0hi[2*s+1], ONES, ONES);
            mma16816(lacc[1], p1lo[2*s], p1hi[2*s], p1lo[2*s+1], p1hi[2*s+1], ONES, ONES);
        }
    }

    // epilogue
    #pragma unroll
    for (int st = 0; st < 2; st++) {
        const float inv_lo = 1.f / lacc[st][0];
        const float inv_hi = 1.f / lacc[st][2];
        float* out_lo = out + ((size_t)n*Ss + rbase + 16*st + g    )*Dd + h*DH;
        float* out_hi = out + ((size_t)n*Ss + rbase + 16*st + g + 8)*Dd + h*DH;
        #pragma unroll
        for (int jv = 0; jv < 8; jv++) {
            float2 vlo = make_float2(o[st][jv][0]*inv_lo, o[st][jv][1]*inv_lo);
            float2 vhi = make_float2(o[st][jv][2]*inv_hi, o[st][jv][3]*inv_hi);
            *(float2*)(out_lo + 8*jv + 2*t) = vlo;
            *(float2*)(out_hi + 8*jv + 2*t) = vhi;
        }
    }
}

// ---------------------------------------------------------------------------
extern "C" void kernel_launch(void* const* d_in, const int* in_sizes, int n_in,
                              void* d_out, int out_size)
{
    const float* x  = (const float*)d_in[0];
    const float* Wq = (const float*)d_in[1];
    const float* bq = (const float*)d_in[2];
    const float* Wk = (const float*)d_in[3];
    const float* bk = (const float*)d_in[4];
    const float* Wv = (const float*)d_in[5];
    const float* bv = (const float*)d_in[6];
    float* out = (float*)d_out;

    dim3 pgrid(Ss/64, Hh, Nn);   // (32, 16, 2)
    qkv_proj_kernel<<<pgrid, 128>>>(x, Wq, bq, Wk, bk, Wv, bv);

    dim3 agrid(Ss/BQ, Hh, Nn);   // (16, 16, 2)
    attn_kernel<<<agrid, 128>>>(out);
}